// round 1
// baseline (speedup 1.0000x reference)
#include <cuda_runtime.h>

#define BB 4
#define SS 2048
#define DD 1024
#define DHE 64
#define SCALE 0.125f

// Scratch (device globals are the sanctioned scratch mechanism).
// g_P order: 0=Qu 1=Ku 2=Vu 3=Qc 4=Kc 5=Vc
static __device__ float g_P[6][BB * SS * DHE];
static __device__ float g_t1[(size_t)BB * SS * SS];  // term1 (lower-tri incl diag, zeros above)
static __device__ float g_sg[(size_t)BB * SS * SS];  // sigmoid gate (strict upper-tri, zeros elsewhere)
static __device__ float g_su[(size_t)BB * SS * SS];  // S_u (only tiles kt<=it valid)

// ---------------------------------------------------------------------------
// K1: projections. out[p] = x @ w[p].  [8192,1024]x[1024,64]
// grid (64,1,6), 256 thr.  Tile 128x64, BK=16, 8x4 micro.
// ---------------------------------------------------------------------------
__global__ void k_proj(const float* __restrict__ x,
                       const float* __restrict__ w0, const float* __restrict__ w1,
                       const float* __restrict__ w2, const float* __restrict__ w3,
                       const float* __restrict__ w4, const float* __restrict__ w5) {
    const int p = blockIdx.z;
    const float* w = w0;
    if (p == 1) w = w1; else if (p == 2) w = w2; else if (p == 3) w = w3;
    else if (p == 4) w = w4; else if (p == 5) w = w5;
    float* out = g_P[p];
    const int row0 = blockIdx.x * 128;

    __shared__ float Xs[16][128];   // [kk][row]
    __shared__ float Ws[16][64];    // [kk][col]

    const int tid = threadIdx.x;
    const int tx = tid & 15, ty = tid >> 4;

    float acc[8][4];
#pragma unroll
    for (int i = 0; i < 8; i++)
#pragma unroll
        for (int j = 0; j < 4; j++) acc[i][j] = 0.f;

    for (int k0 = 0; k0 < DD; k0 += 16) {
#pragma unroll
        for (int t = tid; t < 512; t += 256) {
            int r = t >> 2, c4 = (t & 3) * 4;
            float4 v = *(const float4*)(x + (size_t)(row0 + r) * DD + k0 + c4);
            Xs[c4 + 0][r] = v.x; Xs[c4 + 1][r] = v.y; Xs[c4 + 2][r] = v.z; Xs[c4 + 3][r] = v.w;
        }
        {
            int r = tid >> 4, c4 = (tid & 15) * 4;
            *(float4*)&Ws[r][c4] = *(const float4*)(w + (size_t)(k0 + r) * DHE + c4);
        }
        __syncthreads();
#pragma unroll
        for (int kk = 0; kk < 16; kk++) {
            float xr[8], wr[4];
            *(float4*)&xr[0] = *(float4*)&Xs[kk][ty * 8];
            *(float4*)&xr[4] = *(float4*)&Xs[kk][ty * 8 + 4];
            *(float4*)&wr[0] = *(float4*)&Ws[kk][tx * 4];
#pragma unroll
            for (int i = 0; i < 8; i++)
#pragma unroll
                for (int j = 0; j < 4; j++) acc[i][j] = fmaf(xr[i], wr[j], acc[i][j]);
        }
        __syncthreads();
    }
#pragma unroll
    for (int i = 0; i < 8; i++) {
        float4 v = make_float4(acc[i][0], acc[i][1], acc[i][2], acc[i][3]);
        *(float4*)(out + (size_t)(row0 + ty * 8 + i) * DHE + tx * 4) = v;
    }
}

// ---------------------------------------------------------------------------
// K2: term1 (mode 0) and sigmoid gate (mode 1).  64x64 tiles, K=64.
// grid (32 jt, 32 it, 8 = b + 4*mode), 256 thr.
// Fully-masked tiles are zero-filled (K3 reads them near the diagonal).
// ---------------------------------------------------------------------------
__global__ void k_pair() {
    const int b = blockIdx.z & 3, mode = blockIdx.z >> 2;
    const int it = blockIdx.y, jt = blockIdx.x;
    const int i0 = it * 64, j0 = jt * 64;
    float* out = (mode == 0 ? g_t1 : g_sg) + (size_t)b * SS * SS;
    const int tid = threadIdx.x;
    const int tx = tid & 15, ty = tid >> 4;

    const bool skip = (mode == 0) ? (jt > it) : (jt < it);
    if (skip) {
        for (int t = tid; t < 64 * 16; t += 256) {
            int r = t >> 4, c4 = (t & 15) * 4;
            *(float4*)(out + (size_t)(i0 + r) * SS + j0 + c4) = make_float4(0.f, 0.f, 0.f, 0.f);
        }
        return;
    }

    const float* A  = g_P[mode == 0 ? 3 : 0] + (size_t)b * SS * DHE;  // Qc | Qu
    const float* Bm = g_P[mode == 0 ? 2 : 1] + (size_t)b * SS * DHE;  // Vu | Ku

    __shared__ float As[64][68];  // [d][i]
    __shared__ float Bs[64][68];  // [d][j]

    for (int t = tid; t < 64 * 16; t += 256) {
        int r = t >> 4, c4 = (t & 15) * 4;
        float4 va = *(const float4*)(A + (size_t)(i0 + r) * DHE + c4);
        As[c4 + 0][r] = va.x; As[c4 + 1][r] = va.y; As[c4 + 2][r] = va.z; As[c4 + 3][r] = va.w;
        float4 vb = *(const float4*)(Bm + (size_t)(j0 + r) * DHE + c4);
        Bs[c4 + 0][r] = vb.x; Bs[c4 + 1][r] = vb.y; Bs[c4 + 2][r] = vb.z; Bs[c4 + 3][r] = vb.w;
    }
    __syncthreads();

    float acc[4][4];
#pragma unroll
    for (int i = 0; i < 4; i++)
#pragma unroll
        for (int j = 0; j < 4; j++) acc[i][j] = 0.f;

#pragma unroll
    for (int d = 0; d < 64; d++) {
        float ar[4], br[4];
        *(float4*)ar = *(float4*)&As[d][ty * 4];
        *(float4*)br = *(float4*)&Bs[d][tx * 4];
#pragma unroll
        for (int i = 0; i < 4; i++)
#pragma unroll
            for (int j = 0; j < 4; j++) acc[i][j] = fmaf(ar[i], br[j], acc[i][j]);
    }

#pragma unroll
    for (int r = 0; r < 4; r++) {
        const int gi = i0 + ty * 4 + r;
        float vals[4];
#pragma unroll
        for (int c = 0; c < 4; c++) {
            const int gj = j0 + tx * 4 + c;
            float v = acc[r][c] * SCALE;
            if (mode == 0) {
                v = (gj <= gi) ? v : 0.f;
            } else {
                v = (gj > gi) ? (1.f / (1.f + __expf(-v))) : 0.f;
            }
            vals[c] = v;
        }
        *(float4*)(out + (size_t)gi * SS + j0 + tx * 4) =
            make_float4(vals[0], vals[1], vals[2], vals[3]);
    }
}

// ---------------------------------------------------------------------------
// K3: S_u[i,k] = sum_j term1[i,j] * sig[k,j]   (C = A @ B^T, NT)
// 128x128 tile, BK=16, 8x8 micro, 256 thr.  grid (16 kt, 16 it, 4 b).
// Triangular skip: kt>it tiles are never read -> no work at all.
// j-chunks limited to [kt*128, (it+1)*128) -> ~S^3/6 effective MACs.
// ---------------------------------------------------------------------------
__global__ void __launch_bounds__(256) k_su() {
    const int b = blockIdx.z, it = blockIdx.y, kt = blockIdx.x;
    if (kt > it) return;
    const float* A  = g_t1 + (size_t)b * SS * SS;
    const float* Bm = g_sg + (size_t)b * SS * SS;
    float* C = g_su + (size_t)b * SS * SS;
    const int i0 = it * 128, k0 = kt * 128;

    __shared__ float As[16][132];  // [kk][i]
    __shared__ float Bs[16][132];  // [kk][k]

    const int tid = threadIdx.x;
    const int tx = tid & 15, ty = tid >> 4;

    float acc[8][8];
#pragma unroll
    for (int i = 0; i < 8; i++)
#pragma unroll
        for (int j = 0; j < 8; j++) acc[i][j] = 0.f;

    for (int j0 = kt * 128; j0 < (it + 1) * 128; j0 += 16) {
#pragma unroll
        for (int t = tid; t < 512; t += 256) {
            int r = t >> 2, c4 = (t & 3) * 4;
            float4 va = *(const float4*)(A + (size_t)(i0 + r) * SS + j0 + c4);
            As[c4 + 0][r] = va.x; As[c4 + 1][r] = va.y; As[c4 + 2][r] = va.z; As[c4 + 3][r] = va.w;
            float4 vb = *(const float4*)(Bm + (size_t)(k0 + r) * SS + j0 + c4);
            Bs[c4 + 0][r] = vb.x; Bs[c4 + 1][r] = vb.y; Bs[c4 + 2][r] = vb.z; Bs[c4 + 3][r] = vb.w;
        }
        __syncthreads();
#pragma unroll
        for (int kk = 0; kk < 16; kk++) {
            float ar[8], br[8];
            *(float4*)&ar[0] = *(float4*)&As[kk][ty * 8];
            *(float4*)&ar[4] = *(float4*)&As[kk][ty * 8 + 4];
            *(float4*)&br[0] = *(float4*)&Bs[kk][tx * 8];
            *(float4*)&br[4] = *(float4*)&Bs[kk][tx * 8 + 4];
#pragma unroll
            for (int i = 0; i < 8; i++)
#pragma unroll
                for (int j = 0; j < 8; j++) acc[i][j] = fmaf(ar[i], br[j], acc[i][j]);
        }
        __syncthreads();
    }

#pragma unroll
    for (int i = 0; i < 8; i++) {
        float* row = C + (size_t)(i0 + ty * 8 + i) * SS + k0 + tx * 8;
        *(float4*)(row)     = make_float4(acc[i][0], acc[i][1], acc[i][2], acc[i][3]);
        *(float4*)(row + 4) = make_float4(acc[i][4], acc[i][5], acc[i][6], acc[i][7]);
    }
}

// ---------------------------------------------------------------------------
// K4: flash-style epilogue.  Per (i-tile of 64, batch):
//   loop kt<=it: Sc = Qc_i Kc_k^T * scale; logit = Sc - silu(Su) (+causal -inf);
//   online softmax; O += p @ Vc_k.   out = O / l.
// grid (32 it, 4 b), 256 thr, dynamic smem 3*64*68*4 = 52224 B.
// ---------------------------------------------------------------------------
__global__ void __launch_bounds__(256) k_attn(float* __restrict__ out) {
    const int it = blockIdx.x, b = blockIdx.y;
    const int i0 = it * 64;
    extern __shared__ float sm[];
    float* Qs  = sm;                 // [d][i] stride 68
    float* KVs = sm + 64 * 68;       // Ks: [d][k] stride 68; later Vs: [kk][dh] stride 68
    float* Ps  = sm + 2 * 64 * 68;   // [k][i] stride 68

    const float* Qc = g_P[3] + (size_t)b * SS * DHE;
    const float* Kc = g_P[4] + (size_t)b * SS * DHE;
    const float* Vc = g_P[5] + (size_t)b * SS * DHE;
    const float* Su = g_su + (size_t)b * SS * SS;

    const int tid = threadIdx.x;
    const int tx = tid & 15, ty = tid >> 4;

    // load Qc tile transposed
    for (int t = tid; t < 64 * 16; t += 256) {
        int r = t >> 4, c4 = (t & 15) * 4;
        float4 v = *(const float4*)(Qc + (size_t)(i0 + r) * DHE + c4);
        Qs[(c4 + 0) * 68 + r] = v.x; Qs[(c4 + 1) * 68 + r] = v.y;
        Qs[(c4 + 2) * 68 + r] = v.z; Qs[(c4 + 3) * 68 + r] = v.w;
    }

    float m[4], l[4], O[4][4];
#pragma unroll
    for (int r = 0; r < 4; r++) {
        m[r] = -1e30f; l[r] = 0.f;
#pragma unroll
        for (int c = 0; c < 4; c++) O[r][c] = 0.f;
    }

    for (int kt = 0; kt <= it; kt++) {
        const int k0 = kt * 64;
        __syncthreads();  // prev iter's Ps/Vs reads done; Qs writes visible (iter 0)
        for (int t = tid; t < 64 * 16; t += 256) {
            int r = t >> 4, c4 = (t & 15) * 4;
            float4 v = *(const float4*)(Kc + (size_t)(k0 + r) * DHE + c4);
            KVs[(c4 + 0) * 68 + r] = v.x; KVs[(c4 + 1) * 68 + r] = v.y;
            KVs[(c4 + 2) * 68 + r] = v.z; KVs[(c4 + 3) * 68 + r] = v.w;
        }
        __syncthreads();

        // Sc tile (4x4 per thread)
        float s[4][4];
#pragma unroll
        for (int i = 0; i < 4; i++)
#pragma unroll
            for (int j = 0; j < 4; j++) s[i][j] = 0.f;
#pragma unroll
        for (int d = 0; d < 64; d++) {
            float qr[4], kr[4];
            *(float4*)qr = *(float4*)&Qs[d * 68 + ty * 4];
            *(float4*)kr = *(float4*)&KVs[d * 68 + tx * 4];
#pragma unroll
            for (int i = 0; i < 4; i++)
#pragma unroll
                for (int j = 0; j < 4; j++) s[i][j] = fmaf(qr[i], kr[j], s[i][j]);
        }

        // logits = Sc*scale - silu(Su), causal mask
        float lg[4][4];
#pragma unroll
        for (int r = 0; r < 4; r++) {
            const int gi = i0 + ty * 4 + r;
            float4 su4 = *(const float4*)(Su + (size_t)gi * SS + k0 + tx * 4);
            float su[4] = {su4.x, su4.y, su4.z, su4.w};
#pragma unroll
            for (int c = 0; c < 4; c++) {
                const int gk = k0 + tx * 4 + c;
                const float x = su[c];
                const float silu = x / (1.f + __expf(-x));
                float v = s[r][c] * SCALE - silu;
                if (gk > gi) v = -1e30f;
                lg[r][c] = v;
            }
        }

        // online softmax update
#pragma unroll
        for (int r = 0; r < 4; r++) {
            float mx = fmaxf(fmaxf(lg[r][0], lg[r][1]), fmaxf(lg[r][2], lg[r][3]));
#pragma unroll
            for (int off = 1; off < 16; off <<= 1)
                mx = fmaxf(mx, __shfl_xor_sync(0xffffffffu, mx, off));
            const float mnew = fmaxf(m[r], mx);
            const float corr = __expf(m[r] - mnew);
            m[r] = mnew;
            float ps = 0.f;
#pragma unroll
            for (int c = 0; c < 4; c++) {
                const float p = __expf(lg[r][c] - mnew);
                lg[r][c] = p;
                ps += p;
            }
#pragma unroll
            for (int off = 1; off < 16; off <<= 1)
                ps += __shfl_xor_sync(0xffffffffu, ps, off);
            l[r] = l[r] * corr + ps;
#pragma unroll
            for (int c = 0; c < 4; c++) O[r][c] *= corr;
        }

        // write p transposed: Ps[k][i]
#pragma unroll
        for (int r = 0; r < 4; r++)
#pragma unroll
            for (int c = 0; c < 4; c++)
                Ps[(tx * 4 + c) * 68 + (ty * 4 + r)] = lg[r][c];

        __syncthreads();  // Sc reads of KVs done; Ps visible

        // load Vc tile (plain [kk][dh]) into KVs
        for (int t = tid; t < 64 * 16; t += 256) {
            int r = t >> 4, c4 = (t & 15) * 4;
            *(float4*)&KVs[r * 68 + c4] = *(const float4*)(Vc + (size_t)(k0 + r) * DHE + c4);
        }
        __syncthreads();

        // O += p @ Vc
#pragma unroll
        for (int kk = 0; kk < 64; kk++) {
            float pr[4], vr[4];
            *(float4*)pr = *(float4*)&Ps[kk * 68 + ty * 4];
            *(float4*)vr = *(float4*)&KVs[kk * 68 + tx * 4];
#pragma unroll
            for (int i = 0; i < 4; i++)
#pragma unroll
                for (int j = 0; j < 4; j++) O[i][j] = fmaf(pr[i], vr[j], O[i][j]);
        }
    }

#pragma unroll
    for (int r = 0; r < 4; r++) {
        const float inv = 1.f / l[r];
        float* dst = out + (size_t)b * SS * DHE + (size_t)(i0 + ty * 4 + r) * DHE + tx * 4;
        *(float4*)dst = make_float4(O[r][0] * inv, O[r][1] * inv, O[r][2] * inv, O[r][3] * inv);
    }
}

// ---------------------------------------------------------------------------
extern "C" void kernel_launch(void* const* d_in, const int* in_sizes, int n_in,
                              void* d_out, int out_size) {
    const float* x   = (const float*)d_in[0];
    const float* wqu = (const float*)d_in[1];
    const float* wku = (const float*)d_in[2];
    const float* wvu = (const float*)d_in[3];
    const float* wqc = (const float*)d_in[4];
    const float* wkc = (const float*)d_in[5];
    const float* wvc = (const float*)d_in[6];
    float* out = (float*)d_out;

    k_proj<<<dim3(64, 1, 6), 256>>>(x, wqu, wku, wvu, wqc, wkc, wvc);
    k_pair<<<dim3(32, 32, 8), 256>>>();
    k_su<<<dim3(16, 16, 4), 256>>>();

    const int attn_smem = 3 * 64 * 68 * 4;  // 52224 B
    cudaFuncSetAttribute(k_attn, cudaFuncAttributeMaxDynamicSharedMemorySize, attn_smem);
    k_attn<<<dim3(32, 4), 256, attn_smem>>>(out);
}

// round 2
// speedup vs baseline: 1.4185x; 1.4185x over previous
#include <cuda_runtime.h>

#define BB 4
#define SS 2048
#define DD 1024
#define DHE 64
#define SCALE 0.125f

// Scratch (device globals are the sanctioned scratch mechanism).
// g_P order: 0=Qu 1=Ku 2=Vu 3=Qc 4=Kc 5=Vc
static __device__ float g_P[6][BB * SS * DHE];
static __device__ float g_t1[(size_t)BB * SS * SS];   // term1 (lower-tri incl diag)
static __device__ float g_sg[(size_t)BB * SS * SS];   // sigmoid gate (strict upper-tri)
static __device__ float g_suA[(size_t)BB * SS * SS];  // S_u partial (first half of j-range)
static __device__ float g_suB[(size_t)BB * SS * SS];  // S_u partial (second half)
// split-KV attention partials: up to 4 chunks of 8 k-tiles each
static __device__ float g_am[BB][4][32][64];
static __device__ float g_al[BB][4][32][64];
static __device__ float g_aO[BB][4][32][64 * 64];

// ---------------------------------------------------------------------------
// K1: projections. out[p] = x @ w[p].  [8192,1024]x[1024,64]
// ---------------------------------------------------------------------------
__global__ void k_proj(const float* __restrict__ x,
                       const float* __restrict__ w0, const float* __restrict__ w1,
                       const float* __restrict__ w2, const float* __restrict__ w3,
                       const float* __restrict__ w4, const float* __restrict__ w5) {
    const int p = blockIdx.z;
    const float* w = w0;
    if (p == 1) w = w1; else if (p == 2) w = w2; else if (p == 3) w = w3;
    else if (p == 4) w = w4; else if (p == 5) w = w5;
    float* out = g_P[p];
    const int row0 = blockIdx.x * 128;

    __shared__ float Xs[16][128];
    __shared__ float Ws[16][64];

    const int tid = threadIdx.x;
    const int tx = tid & 15, ty = tid >> 4;

    float acc[8][4];
#pragma unroll
    for (int i = 0; i < 8; i++)
#pragma unroll
        for (int j = 0; j < 4; j++) acc[i][j] = 0.f;

    for (int k0 = 0; k0 < DD; k0 += 16) {
#pragma unroll
        for (int t = tid; t < 512; t += 256) {
            int r = t >> 2, c4 = (t & 3) * 4;
            float4 v = *(const float4*)(x + (size_t)(row0 + r) * DD + k0 + c4);
            Xs[c4 + 0][r] = v.x; Xs[c4 + 1][r] = v.y; Xs[c4 + 2][r] = v.z; Xs[c4 + 3][r] = v.w;
        }
        {
            int r = tid >> 4, c4 = (tid & 15) * 4;
            *(float4*)&Ws[r][c4] = *(const float4*)(w + (size_t)(k0 + r) * DHE + c4);
        }
        __syncthreads();
#pragma unroll
        for (int kk = 0; kk < 16; kk++) {
            float xr[8], wr[4];
            *(float4*)&xr[0] = *(float4*)&Xs[kk][ty * 8];
            *(float4*)&xr[4] = *(float4*)&Xs[kk][ty * 8 + 4];
            *(float4*)&wr[0] = *(float4*)&Ws[kk][tx * 4];
#pragma unroll
            for (int i = 0; i < 8; i++)
#pragma unroll
                for (int j = 0; j < 4; j++) acc[i][j] = fmaf(xr[i], wr[j], acc[i][j]);
        }
        __syncthreads();
    }
#pragma unroll
    for (int i = 0; i < 8; i++) {
        float4 v = make_float4(acc[i][0], acc[i][1], acc[i][2], acc[i][3]);
        *(float4*)(out + (size_t)(row0 + ty * 8 + i) * DHE + tx * 4) = v;
    }
}

// ---------------------------------------------------------------------------
// K2: term1 (mode 0) and sigmoid gate (mode 1).  64x64 tiles, K=64.
// Zero-fill only the masked tiles k_su actually reads (adjacent to the
// 128-tile diagonal); all other masked tiles return immediately.
// ---------------------------------------------------------------------------
__global__ void k_pair() {
    const int b = blockIdx.z & 3, mode = blockIdx.z >> 2;
    const int it = blockIdx.y, jt = blockIdx.x;
    const int i0 = it * 64, j0 = jt * 64;
    float* out = (mode == 0 ? g_t1 : g_sg) + (size_t)b * SS * SS;
    const int tid = threadIdx.x;
    const int tx = tid & 15, ty = tid >> 4;

    const bool skip = (mode == 0) ? (jt > it) : (jt < it);
    if (skip) {
        const bool needed = (mode == 0)
            ? (jt == it + 1 && (it & 1) == 0)    // term1: tile just right of diag, even row
            : (jt == it - 1 && (it & 1) == 1);   // sig:   tile just left of diag, odd row
        if (!needed) return;
        for (int t = tid; t < 64 * 16; t += 256) {
            int r = t >> 4, c4 = (t & 15) * 4;
            *(float4*)(out + (size_t)(i0 + r) * SS + j0 + c4) = make_float4(0.f, 0.f, 0.f, 0.f);
        }
        return;
    }

    const float* A  = g_P[mode == 0 ? 3 : 0] + (size_t)b * SS * DHE;  // Qc | Qu
    const float* Bm = g_P[mode == 0 ? 2 : 1] + (size_t)b * SS * DHE;  // Vu | Ku

    __shared__ float As[64][68];
    __shared__ float Bs[64][68];

    for (int t = tid; t < 64 * 16; t += 256) {
        int r = t >> 4, c4 = (t & 15) * 4;
        float4 va = *(const float4*)(A + (size_t)(i0 + r) * DHE + c4);
        As[c4 + 0][r] = va.x; As[c4 + 1][r] = va.y; As[c4 + 2][r] = va.z; As[c4 + 3][r] = va.w;
        float4 vb = *(const float4*)(Bm + (size_t)(j0 + r) * DHE + c4);
        Bs[c4 + 0][r] = vb.x; Bs[c4 + 1][r] = vb.y; Bs[c4 + 2][r] = vb.z; Bs[c4 + 3][r] = vb.w;
    }
    __syncthreads();

    float acc[4][4];
#pragma unroll
    for (int i = 0; i < 4; i++)
#pragma unroll
        for (int j = 0; j < 4; j++) acc[i][j] = 0.f;

#pragma unroll
    for (int d = 0; d < 64; d++) {
        float ar[4], br[4];
        *(float4*)ar = *(float4*)&As[d][ty * 4];
        *(float4*)br = *(float4*)&Bs[d][tx * 4];
#pragma unroll
        for (int i = 0; i < 4; i++)
#pragma unroll
            for (int j = 0; j < 4; j++) acc[i][j] = fmaf(ar[i], br[j], acc[i][j]);
    }

#pragma unroll
    for (int r = 0; r < 4; r++) {
        const int gi = i0 + ty * 4 + r;
        float vals[4];
#pragma unroll
        for (int c = 0; c < 4; c++) {
            const int gj = j0 + tx * 4 + c;
            float v = acc[r][c] * SCALE;
            if (mode == 0) {
                v = (gj <= gi) ? v : 0.f;
            } else {
                v = (gj > gi) ? (1.f / (1.f + __expf(-v))) : 0.f;
            }
            vals[c] = v;
        }
        *(float4*)(out + (size_t)gi * SS + j0 + tx * 4) =
            make_float4(vals[0], vals[1], vals[2], vals[3]);
    }
}

// ---------------------------------------------------------------------------
// K3: S_u[i,k] = sum_j term1[i,j] * sig[k,j]   (C = A @ B^T, NT)
// 128x128 tile, BK=16, 8x8 micro, 256 thr.
// Lower-tri pairs enumerated longest-diagonal-first; each pair's j-range is
// halved into two blocks (seg 0 -> g_suA, seg 1 -> g_suB) so no block
// exceeds 64 BK-chunks (the balanced per-SM share is ~88).
// grid (136 pairs * 2 segs, 1, 4)
// ---------------------------------------------------------------------------
__global__ void __launch_bounds__(256) k_su() {
    const int b = blockIdx.z;
    const int seg = blockIdx.x & 1;
    int pp = blockIdx.x >> 1;
    int d = 15;                       // diagonal = it - kt, descending (longest first)
    while (pp >= 16 - d) { pp -= 16 - d; d--; }
    const int kt = pp, it = pp + d;

    const float* A  = g_t1 + (size_t)b * SS * SS;
    const float* Bm = g_sg + (size_t)b * SS * SS;
    float* C = (seg ? g_suB : g_suA) + (size_t)b * SS * SS;
    const int i0 = it * 128, k0 = kt * 128;

    int jbeg = k0, jend = (it + 1) * 128;
    const int mid = jbeg + ((jend - jbeg) >> 1);   // (d+1)*64, multiple of 64
    if (seg == 0) jend = mid; else jbeg = mid;

    __shared__ float As[16][132];
    __shared__ float Bs[16][132];

    const int tid = threadIdx.x;
    const int tx = tid & 15, ty = tid >> 4;

    float acc[8][8];
#pragma unroll
    for (int i = 0; i < 8; i++)
#pragma unroll
        for (int j = 0; j < 8; j++) acc[i][j] = 0.f;

    for (int j0 = jbeg; j0 < jend; j0 += 16) {
#pragma unroll
        for (int t = tid; t < 512; t += 256) {
            int r = t >> 2, c4 = (t & 3) * 4;
            float4 va = *(const float4*)(A + (size_t)(i0 + r) * SS + j0 + c4);
            As[c4 + 0][r] = va.x; As[c4 + 1][r] = va.y; As[c4 + 2][r] = va.z; As[c4 + 3][r] = va.w;
            float4 vb = *(const float4*)(Bm + (size_t)(k0 + r) * SS + j0 + c4);
            Bs[c4 + 0][r] = vb.x; Bs[c4 + 1][r] = vb.y; Bs[c4 + 2][r] = vb.z; Bs[c4 + 3][r] = vb.w;
        }
        __syncthreads();
#pragma unroll
        for (int kk = 0; kk < 16; kk++) {
            float ar[8], br[8];
            *(float4*)&ar[0] = *(float4*)&As[kk][ty * 8];
            *(float4*)&ar[4] = *(float4*)&As[kk][ty * 8 + 4];
            *(float4*)&br[0] = *(float4*)&Bs[kk][tx * 8];
            *(float4*)&br[4] = *(float4*)&Bs[kk][tx * 8 + 4];
#pragma unroll
            for (int i = 0; i < 8; i++)
#pragma unroll
                for (int j = 0; j < 8; j++) acc[i][j] = fmaf(ar[i], br[j], acc[i][j]);
        }
        __syncthreads();
    }

#pragma unroll
    for (int i = 0; i < 8; i++) {
        float* row = C + (size_t)(i0 + ty * 8 + i) * SS + k0 + tx * 8;
        *(float4*)(row)     = make_float4(acc[i][0], acc[i][1], acc[i][2], acc[i][3]);
        *(float4*)(row + 4) = make_float4(acc[i][4], acc[i][5], acc[i][6], acc[i][7]);
    }
}

// ---------------------------------------------------------------------------
// K4: split-KV flash attention partial.  grid (32 it, 4 chunk, 4 b), 256 thr.
// Each block processes k-tiles kt in [8*chunk, min(8*chunk+8, it+1)) and
// writes unnormalized partial (m, l, O) to scratch.  S_u = g_suA + g_suB.
// ---------------------------------------------------------------------------
__global__ void __launch_bounds__(256) k_attn_part() {
    const int it = blockIdx.x, chunk = blockIdx.y, b = blockIdx.z;
    if (chunk * 8 > it) return;
    const int kt_beg = chunk * 8;
    const int kt_end = min(kt_beg + 8, it + 1);
    const int i0 = it * 64;

    extern __shared__ float sm[];
    float* Qs  = sm;                 // [d][i] stride 68
    float* KVs = sm + 64 * 68;       // Ks: [d][k]; later Vs: [kk][dh]
    float* Ps  = sm + 2 * 64 * 68;   // [k][i]

    const float* Qc  = g_P[3] + (size_t)b * SS * DHE;
    const float* Kc  = g_P[4] + (size_t)b * SS * DHE;
    const float* Vc  = g_P[5] + (size_t)b * SS * DHE;
    const float* SuA = g_suA + (size_t)b * SS * SS;
    const float* SuB = g_suB + (size_t)b * SS * SS;

    const int tid = threadIdx.x;
    const int tx = tid & 15, ty = tid >> 4;

    for (int t = tid; t < 64 * 16; t += 256) {
        int r = t >> 4, c4 = (t & 15) * 4;
        float4 v = *(const float4*)(Qc + (size_t)(i0 + r) * DHE + c4);
        Qs[(c4 + 0) * 68 + r] = v.x; Qs[(c4 + 1) * 68 + r] = v.y;
        Qs[(c4 + 2) * 68 + r] = v.z; Qs[(c4 + 3) * 68 + r] = v.w;
    }

    float m[4], l[4], O[4][4];
#pragma unroll
    for (int r = 0; r < 4; r++) {
        m[r] = -1e30f; l[r] = 0.f;
#pragma unroll
        for (int c = 0; c < 4; c++) O[r][c] = 0.f;
    }

    for (int kt = kt_beg; kt < kt_end; kt++) {
        const int k0 = kt * 64;
        __syncthreads();
        for (int t = tid; t < 64 * 16; t += 256) {
            int r = t >> 4, c4 = (t & 15) * 4;
            float4 v = *(const float4*)(Kc + (size_t)(k0 + r) * DHE + c4);
            KVs[(c4 + 0) * 68 + r] = v.x; KVs[(c4 + 1) * 68 + r] = v.y;
            KVs[(c4 + 2) * 68 + r] = v.z; KVs[(c4 + 3) * 68 + r] = v.w;
        }
        __syncthreads();

        float s[4][4];
#pragma unroll
        for (int i = 0; i < 4; i++)
#pragma unroll
            for (int j = 0; j < 4; j++) s[i][j] = 0.f;
#pragma unroll
        for (int d = 0; d < 64; d++) {
            float qr[4], kr[4];
            *(float4*)qr = *(float4*)&Qs[d * 68 + ty * 4];
            *(float4*)kr = *(float4*)&KVs[d * 68 + tx * 4];
#pragma unroll
            for (int i = 0; i < 4; i++)
#pragma unroll
                for (int j = 0; j < 4; j++) s[i][j] = fmaf(qr[i], kr[j], s[i][j]);
        }

        float lg[4][4];
#pragma unroll
        for (int r = 0; r < 4; r++) {
            const int gi = i0 + ty * 4 + r;
            float4 a4 = *(const float4*)(SuA + (size_t)gi * SS + k0 + tx * 4);
            float4 b4 = *(const float4*)(SuB + (size_t)gi * SS + k0 + tx * 4);
            float su[4] = {a4.x + b4.x, a4.y + b4.y, a4.z + b4.z, a4.w + b4.w};
#pragma unroll
            for (int c = 0; c < 4; c++) {
                const int gk = k0 + tx * 4 + c;
                const float x = su[c];
                const float silu = x / (1.f + __expf(-x));
                float v = s[r][c] * SCALE - silu;
                if (gk > gi) v = -1e30f;
                lg[r][c] = v;
            }
        }

#pragma unroll
        for (int r = 0; r < 4; r++) {
            float mx = fmaxf(fmaxf(lg[r][0], lg[r][1]), fmaxf(lg[r][2], lg[r][3]));
#pragma unroll
            for (int off = 1; off < 16; off <<= 1)
                mx = fmaxf(mx, __shfl_xor_sync(0xffffffffu, mx, off));
            const float mnew = fmaxf(m[r], mx);
            const float corr = __expf(m[r] - mnew);
            m[r] = mnew;
            float ps = 0.f;
#pragma unroll
            for (int c = 0; c < 4; c++) {
                const float p = __expf(lg[r][c] - mnew);
                lg[r][c] = p;
                ps += p;
            }
#pragma unroll
            for (int off = 1; off < 16; off <<= 1)
                ps += __shfl_xor_sync(0xffffffffu, ps, off);
            l[r] = l[r] * corr + ps;
#pragma unroll
            for (int c = 0; c < 4; c++) O[r][c] *= corr;
        }

#pragma unroll
        for (int r = 0; r < 4; r++)
#pragma unroll
            for (int c = 0; c < 4; c++)
                Ps[(tx * 4 + c) * 68 + (ty * 4 + r)] = lg[r][c];

        __syncthreads();

        for (int t = tid; t < 64 * 16; t += 256) {
            int r = t >> 4, c4 = (t & 15) * 4;
            *(float4*)&KVs[r * 68 + c4] = *(const float4*)(Vc + (size_t)(k0 + r) * DHE + c4);
        }
        __syncthreads();

#pragma unroll
        for (int kk = 0; kk < 64; kk++) {
            float pr[4], vr[4];
            *(float4*)pr = *(float4*)&Ps[kk * 68 + ty * 4];
            *(float4*)vr = *(float4*)&KVs[kk * 68 + tx * 4];
#pragma unroll
            for (int i = 0; i < 4; i++)
#pragma unroll
                for (int j = 0; j < 4; j++) O[i][j] = fmaf(pr[i], vr[j], O[i][j]);
        }
    }

    // write partials (unnormalized)
#pragma unroll
    for (int r = 0; r < 4; r++) {
        const int lr = ty * 4 + r;
        if (tx == 0) {
            g_am[b][chunk][it][lr] = m[r];
            g_al[b][chunk][it][lr] = l[r];
        }
        *(float4*)&g_aO[b][chunk][it][lr * 64 + tx * 4] =
            make_float4(O[r][0], O[r][1], O[r][2], O[r][3]);
    }
}

// ---------------------------------------------------------------------------
// K5: combine split-KV partials (deterministic, fixed order).
// grid (32 it, 4 b), 256 thr.  Each thread: one row r, 16 cols.
// ---------------------------------------------------------------------------
__global__ void k_comb(float* __restrict__ out) {
    const int it = blockIdx.x, b = blockIdx.y;
    const int nch = it / 8 + 1;
    const int tid = threadIdx.x;
    const int r = tid >> 2;
    const int c0 = (tid & 3) * 16;

    float M = -1e30f;
#pragma unroll
    for (int c = 0; c < 4; c++)
        if (c < nch) M = fmaxf(M, g_am[b][c][it][r]);

    float w[4] = {0.f, 0.f, 0.f, 0.f};
    float lt = 0.f;
#pragma unroll
    for (int c = 0; c < 4; c++)
        if (c < nch) {
            const float wv = __expf(g_am[b][c][it][r] - M);
            w[c] = wv;
            lt += g_al[b][c][it][r] * wv;
        }
    const float inv = 1.f / lt;

    float* dst = out + ((size_t)b * SS + it * 64 + r) * DHE + c0;
#pragma unroll
    for (int j4 = 0; j4 < 4; j4++) {
        float4 acc = make_float4(0.f, 0.f, 0.f, 0.f);
#pragma unroll
        for (int c = 0; c < 4; c++)
            if (c < nch) {
                float4 v = *(const float4*)&g_aO[b][c][it][r * 64 + c0 + j4 * 4];
                acc.x = fmaf(v.x, w[c], acc.x);
                acc.y = fmaf(v.y, w[c], acc.y);
                acc.z = fmaf(v.z, w[c], acc.z);
                acc.w = fmaf(v.w, w[c], acc.w);
            }
        *(float4*)(dst + j4 * 4) =
            make_float4(acc.x * inv, acc.y * inv, acc.z * inv, acc.w * inv);
    }
}

// ---------------------------------------------------------------------------
extern "C" void kernel_launch(void* const* d_in, const int* in_sizes, int n_in,
                              void* d_out, int out_size) {
    const float* x   = (const float*)d_in[0];
    const float* wqu = (const float*)d_in[1];
    const float* wku = (const float*)d_in[2];
    const float* wvu = (const float*)d_in[3];
    const float* wqc = (const float*)d_in[4];
    const float* wkc = (const float*)d_in[5];
    const float* wvc = (const float*)d_in[6];
    float* out = (float*)d_out;

    k_proj<<<dim3(64, 1, 6), 256>>>(x, wqu, wku, wvu, wqc, wkc, wvc);
    k_pair<<<dim3(32, 32, 8), 256>>>();
    k_su<<<dim3(272, 1, 4), 256>>>();

    const int attn_smem = 3 * 64 * 68 * 4;  // 52224 B
    cudaFuncSetAttribute(k_attn_part, cudaFuncAttributeMaxDynamicSharedMemorySize, attn_smem);
    k_attn_part<<<dim3(32, 4, 4), 256, attn_smem>>>();
    k_comb<<<dim3(32, 4), 256>>>(out);
}

// round 4
// speedup vs baseline: 2.0989x; 1.4797x over previous
#include <cuda_runtime.h>
#include <cuda_bf16.h>
#include <cstdint>

#define BB 4
#define SS 2048
#define DD 1024
#define DHE 64
#define SCALE 0.125f

// ---------------- scratch (device globals) ----------------
static __device__ float g_P[6][BB * SS * DHE];  // 0=Qu 1=Ku 2=Vu 3=Qc 4=Kc 5=Vc
static __device__ __nv_bfloat16 g_t1h[(size_t)BB * SS * SS];
static __device__ __nv_bfloat16 g_t1l[(size_t)BB * SS * SS];
static __device__ __nv_bfloat16 g_sgh[(size_t)BB * SS * SS];
static __device__ __nv_bfloat16 g_sgl[(size_t)BB * SS * SS];
static __device__ float g_suA[(size_t)BB * SS * SS];
static __device__ float g_suB[(size_t)BB * SS * SS];
static __device__ float g_am[BB][4][32][64];
static __device__ float g_al[BB][4][32][64];
static __device__ float g_aO[BB][4][32][64 * 64];

// ---------------- helpers (compute_103-safe: no 'a' features) ----------------
__device__ __forceinline__ uint32_t smem_to_u32(const void* p) {
    uint32_t a;
    asm("{ .reg .u64 t; cvta.to.shared.u64 t, %1; cvt.u32.u64 %0, t; }" : "=r"(a) : "l"(p));
    return a;
}
#define SW128(o) ((o) ^ (((o) >> 3) & 0x70))

__device__ __forceinline__ void ldsm4(uint32_t* r, uint32_t addr) {
    asm volatile("ldmatrix.sync.aligned.m8n8.x4.shared.b16 {%0,%1,%2,%3}, [%4];"
        : "=r"(r[0]), "=r"(r[1]), "=r"(r[2]), "=r"(r[3]) : "r"(addr));
}
__device__ __forceinline__ void mma16816(float* c, const uint32_t* a,
                                         uint32_t b0, uint32_t b1) {
    asm volatile("mma.sync.aligned.m16n8k16.row.col.f32.bf16.bf16.f32 "
        "{%0,%1,%2,%3}, {%4,%5,%6,%7}, {%8,%9}, {%0,%1,%2,%3};"
        : "+f"(c[0]), "+f"(c[1]), "+f"(c[2]), "+f"(c[3])
        : "r"(a[0]), "r"(a[1]), "r"(a[2]), "r"(a[3]), "r"(b0), "r"(b1));
}

// ---------------------------------------------------------------------------
// K1: projections (unchanged)
// ---------------------------------------------------------------------------
__global__ void k_proj(const float* __restrict__ x,
                       const float* __restrict__ w0, const float* __restrict__ w1,
                       const float* __restrict__ w2, const float* __restrict__ w3,
                       const float* __restrict__ w4, const float* __restrict__ w5) {
    const int p = blockIdx.z;
    const float* w = w0;
    if (p == 1) w = w1; else if (p == 2) w = w2; else if (p == 3) w = w3;
    else if (p == 4) w = w4; else if (p == 5) w = w5;
    float* out = g_P[p];
    const int row0 = blockIdx.x * 128;

    __shared__ float Xs[16][128];
    __shared__ float Ws[16][64];

    const int tid = threadIdx.x;
    const int tx = tid & 15, ty = tid >> 4;

    float acc[8][4];
#pragma unroll
    for (int i = 0; i < 8; i++)
#pragma unroll
        for (int j = 0; j < 4; j++) acc[i][j] = 0.f;

    for (int k0 = 0; k0 < DD; k0 += 16) {
#pragma unroll
        for (int t = tid; t < 512; t += 256) {
            int r = t >> 2, c4 = (t & 3) * 4;
            float4 v = *(const float4*)(x + (size_t)(row0 + r) * DD + k0 + c4);
            Xs[c4 + 0][r] = v.x; Xs[c4 + 1][r] = v.y; Xs[c4 + 2][r] = v.z; Xs[c4 + 3][r] = v.w;
        }
        {
            int r = tid >> 4, c4 = (tid & 15) * 4;
            *(float4*)&Ws[r][c4] = *(const float4*)(w + (size_t)(k0 + r) * DHE + c4);
        }
        __syncthreads();
#pragma unroll
        for (int kk = 0; kk < 16; kk++) {
            float xr[8], wr[4];
            *(float4*)&xr[0] = *(float4*)&Xs[kk][ty * 8];
            *(float4*)&xr[4] = *(float4*)&Xs[kk][ty * 8 + 4];
            *(float4*)&wr[0] = *(float4*)&Ws[kk][tx * 4];
#pragma unroll
            for (int i = 0; i < 8; i++)
#pragma unroll
                for (int j = 0; j < 4; j++) acc[i][j] = fmaf(xr[i], wr[j], acc[i][j]);
        }
        __syncthreads();
    }
#pragma unroll
    for (int i = 0; i < 8; i++) {
        float4 v = make_float4(acc[i][0], acc[i][1], acc[i][2], acc[i][3]);
        *(float4*)(out + (size_t)(row0 + ty * 8 + i) * DHE + tx * 4) = v;
    }
}

// ---------------------------------------------------------------------------
// K2: term1 / sigmoid gate -> bf16 hi/lo pairs.  64x64 tiles, K=64.
// ---------------------------------------------------------------------------
__global__ void k_pair() {
    const int b = blockIdx.z & 3, mode = blockIdx.z >> 2;
    const int it = blockIdx.y, jt = blockIdx.x;
    const int i0 = it * 64, j0 = jt * 64;
    const size_t boff = (size_t)b * SS * SS;
    __nv_bfloat16* outh = (mode == 0 ? g_t1h : g_sgh) + boff;
    __nv_bfloat16* outl = (mode == 0 ? g_t1l : g_sgl) + boff;
    const int tid = threadIdx.x;
    const int tx = tid & 15, ty = tid >> 4;

    const bool skip = (mode == 0) ? (jt > it) : (jt < it);
    if (skip) {
        const bool needed = (mode == 0)
            ? (jt == it + 1 && (it & 1) == 0)
            : (jt == it - 1 && (it & 1) == 1);
        if (!needed) return;
        const uint4 z = make_uint4(0, 0, 0, 0);
        for (int t = tid; t < 64 * 8; t += 256) {
            int r = t >> 3, c8 = (t & 7) * 8;
            *(uint4*)(outh + (size_t)(i0 + r) * SS + j0 + c8) = z;
            *(uint4*)(outl + (size_t)(i0 + r) * SS + j0 + c8) = z;
        }
        return;
    }

    const float* A  = g_P[mode == 0 ? 3 : 0] + (size_t)b * SS * DHE;  // Qc | Qu
    const float* Bm = g_P[mode == 0 ? 2 : 1] + (size_t)b * SS * DHE;  // Vu | Ku

    __shared__ float As[64][68];
    __shared__ float Bs[64][68];

    for (int t = tid; t < 64 * 16; t += 256) {
        int r = t >> 4, c4 = (t & 15) * 4;
        float4 va = *(const float4*)(A + (size_t)(i0 + r) * DHE + c4);
        As[c4 + 0][r] = va.x; As[c4 + 1][r] = va.y; As[c4 + 2][r] = va.z; As[c4 + 3][r] = va.w;
        float4 vb = *(const float4*)(Bm + (size_t)(j0 + r) * DHE + c4);
        Bs[c4 + 0][r] = vb.x; Bs[c4 + 1][r] = vb.y; Bs[c4 + 2][r] = vb.z; Bs[c4 + 3][r] = vb.w;
    }
    __syncthreads();

    float acc[4][4];
#pragma unroll
    for (int i = 0; i < 4; i++)
#pragma unroll
        for (int j = 0; j < 4; j++) acc[i][j] = 0.f;

#pragma unroll
    for (int d = 0; d < 64; d++) {
        float ar[4], br[4];
        *(float4*)ar = *(float4*)&As[d][ty * 4];
        *(float4*)br = *(float4*)&Bs[d][tx * 4];
#pragma unroll
        for (int i = 0; i < 4; i++)
#pragma unroll
            for (int j = 0; j < 4; j++) acc[i][j] = fmaf(ar[i], br[j], acc[i][j]);
    }

#pragma unroll
    for (int r = 0; r < 4; r++) {
        const int gi = i0 + ty * 4 + r;
        union { __nv_bfloat162 b2[2]; uint2 u; } hu, lu;
#pragma unroll
        for (int c2 = 0; c2 < 2; c2++) {
            __nv_bfloat16 hh[2], ll[2];
#pragma unroll
            for (int q = 0; q < 2; q++) {
                const int c = c2 * 2 + q;
                const int gj = j0 + tx * 4 + c;
                float v = acc[r][c] * SCALE;
                if (mode == 0) {
                    v = (gj <= gi) ? v : 0.f;
                } else {
                    v = (gj > gi) ? (1.f / (1.f + __expf(-v))) : 0.f;
                }
                hh[q] = __float2bfloat16(v);
                ll[q] = __float2bfloat16(v - __bfloat162float(hh[q]));
            }
            hu.b2[c2] = __halves2bfloat162(hh[0], hh[1]);
            lu.b2[c2] = __halves2bfloat162(ll[0], ll[1]);
        }
        *(uint2*)(outh + (size_t)gi * SS + j0 + tx * 4) = hu.u;
        *(uint2*)(outl + (size_t)gi * SS + j0 + tx * 4) = lu.u;
    }
}

// ---------------------------------------------------------------------------
// K3: S_u via mma.sync bf16x2-split.  C[i,k] = sum_j t1[i,j]*sg[k,j]
// Per CTA: M=128 (i) x N=128 (k), j-chunks of 64; products hh+hl+lh in fp32
// register accumulators.  8 warps (4x2), warp tile 32x64, m16n8k16.
// 2-stage cp.async double buffer, SW128-swizzled 128B-row tiles.
// grid (272 = 136 pairs * 2 segs, 1, 4 b), 256 thr, 132096 B dyn smem.
// ---------------------------------------------------------------------------
__global__ void __launch_bounds__(256) k_su_mma() {
    extern __shared__ char smem[];
    const uint32_t tiles = (smem_to_u32(smem) + 1023u) & ~1023u;

    const int b = blockIdx.z;
    const int seg = blockIdx.x & 1;
    int pp = blockIdx.x >> 1;
    int d = 15;
    while (pp >= 16 - d) { pp -= 16 - d; d--; }
    const int kt = pp, it = pp + d;
    const int i0 = it * 128, k0 = kt * 128;

    int jbeg = k0, jend = (it + 1) * 128;
    const int mid = jbeg + ((jend - jbeg) >> 1);
    if (seg == 0) jend = mid; else jbeg = mid;
    const int nch = (jend - jbeg) >> 6;

    const int tid = threadIdx.x;
    const int wid = tid >> 5, lane = tid & 31;

    // loader assignment: tile (0=Ah 1=Al 2=Bh 3=Bl), 16B column, 16 rows
    const int ltile = tid >> 6;
    const int llane = tid & 63;
    const int rl = llane >> 3;       // base row 0..7
    const int c16 = llane & 7;       // 16B column index within 128B row
    const size_t boff = (size_t)b * SS * SS;
    const __nv_bfloat16* src =
        (ltile == 0) ? g_t1h + boff + (size_t)i0 * SS :
        (ltile == 1) ? g_t1l + boff + (size_t)i0 * SS :
        (ltile == 2) ? g_sgh + boff + (size_t)k0 * SS :
                       g_sgl + boff + (size_t)k0 * SS;
    const __nv_bfloat16* gbase = src + (size_t)rl * SS + c16 * 8;
    const uint32_t tsm = tiles + ltile * 16384;

#define SU_LOAD_CHUNK(stage, j0v) do { \
    const __nv_bfloat16* _g = gbase + (j0v); \
    const uint32_t _base = tsm + (stage) * 65536; \
    _Pragma("unroll") \
    for (int q = 0; q < 16; q++) { \
        uint32_t so = (uint32_t)((q * 8 + rl) * 128 + c16 * 16); \
        uint32_t sa = _base + SW128(so); \
        asm volatile("cp.async.cg.shared.global [%0], [%1], 16;" :: "r"(sa), "l"(_g + (size_t)q * 8 * SS)); \
    } \
    asm volatile("cp.async.commit_group;"); \
} while (0)

    float acc[2][8][4];
#pragma unroll
    for (int mf = 0; mf < 2; mf++)
#pragma unroll
        for (int nf = 0; nf < 8; nf++)
#pragma unroll
            for (int q = 0; q < 4; q++) acc[mf][nf][q] = 0.f;

    const int wm = wid >> 1, wn = wid & 1;
    const int lrow = lane & 15;
    const uint32_t kbl = (lane >> 4) * 16;   // 16B half within 32B k-step

    SU_LOAD_CHUNK(0, jbeg);

    for (int i = 0; i < nch; i++) {
        const int s = i & 1;
        if (i + 1 < nch) {
            SU_LOAD_CHUNK(s ^ 1, jbeg + (i + 1) * 64);
            asm volatile("cp.async.wait_group 1;");
        } else {
            asm volatile("cp.async.wait_group 0;");
        }
        __syncthreads();

        const uint32_t stAh = tiles + s * 65536;
        const uint32_t stAl = stAh + 16384;
        const uint32_t stBh = stAh + 32768;
        const uint32_t stBl = stAh + 49152;

#pragma unroll
        for (int ks = 0; ks < 4; ks++) {
            const uint32_t kb = ks * 32 + kbl;
            uint32_t ah[2][4], al[2][4], bh[4][4], bl[4][4];
#pragma unroll
            for (int mf = 0; mf < 2; mf++) {
                const uint32_t off = SW128((uint32_t)((wm * 32 + mf * 16 + lrow) * 128) + kb);
                ldsm4(ah[mf], stAh + off);
                ldsm4(al[mf], stAl + off);
            }
#pragma unroll
            for (int np = 0; np < 4; np++) {
                const uint32_t off = SW128((uint32_t)((wn * 64 + np * 16 + lrow) * 128) + kb);
                ldsm4(bh[np], stBh + off);
                ldsm4(bl[np], stBl + off);
            }
#pragma unroll
            for (int mf = 0; mf < 2; mf++)
#pragma unroll
                for (int nf = 0; nf < 8; nf++) {
                    const int np = nf >> 1, sel = nf & 1;
                    mma16816(acc[mf][nf], ah[mf], bh[np][sel], bh[np][sel + 2]);
                    mma16816(acc[mf][nf], ah[mf], bl[np][sel], bl[np][sel + 2]);
                    mma16816(acc[mf][nf], al[mf], bh[np][sel], bh[np][sel + 2]);
                }
        }
        __syncthreads();
    }
#undef SU_LOAD_CHUNK

    float* C = (seg ? g_suB : g_suA) + boff;
    const int rr = lane >> 2, cc = (lane & 3) * 2;
#pragma unroll
    for (int mf = 0; mf < 2; mf++) {
        const int gr = i0 + wm * 32 + mf * 16 + rr;
#pragma unroll
        for (int nf = 0; nf < 8; nf++) {
            const int gc = k0 + wn * 64 + nf * 8 + cc;
            *(float2*)(C + (size_t)gr * SS + gc) = make_float2(acc[mf][nf][0], acc[mf][nf][1]);
            *(float2*)(C + (size_t)(gr + 8) * SS + gc) = make_float2(acc[mf][nf][2], acc[mf][nf][3]);
        }
    }
}

// ---------------------------------------------------------------------------
// K4: split-KV flash attention partial (unchanged from R2)
// ---------------------------------------------------------------------------
__global__ void __launch_bounds__(256) k_attn_part() {
    const int it = blockIdx.x, chunk = blockIdx.y, b = blockIdx.z;
    if (chunk * 8 > it) return;
    const int kt_beg = chunk * 8;
    const int kt_end = min(kt_beg + 8, it + 1);
    const int i0 = it * 64;

    extern __shared__ float sm[];
    float* Qs  = sm;
    float* KVs = sm + 64 * 68;
    float* Ps  = sm + 2 * 64 * 68;

    const float* Qc  = g_P[3] + (size_t)b * SS * DHE;
    const float* Kc  = g_P[4] + (size_t)b * SS * DHE;
    const float* Vc  = g_P[5] + (size_t)b * SS * DHE;
    const float* SuA = g_suA + (size_t)b * SS * SS;
    const float* SuB = g_suB + (size_t)b * SS * SS;

    const int tid = threadIdx.x;
    const int tx = tid & 15, ty = tid >> 4;

    for (int t = tid; t < 64 * 16; t += 256) {
        int r = t >> 4, c4 = (t & 15) * 4;
        float4 v = *(const float4*)(Qc + (size_t)(i0 + r) * DHE + c4);
        Qs[(c4 + 0) * 68 + r] = v.x; Qs[(c4 + 1) * 68 + r] = v.y;
        Qs[(c4 + 2) * 68 + r] = v.z; Qs[(c4 + 3) * 68 + r] = v.w;
    }

    float m[4], l[4], O[4][4];
#pragma unroll
    for (int r = 0; r < 4; r++) {
        m[r] = -1e30f; l[r] = 0.f;
#pragma unroll
        for (int c = 0; c < 4; c++) O[r][c] = 0.f;
    }

    for (int kt = kt_beg; kt < kt_end; kt++) {
        const int k0 = kt * 64;
        __syncthreads();
        for (int t = tid; t < 64 * 16; t += 256) {
            int r = t >> 4, c4 = (t & 15) * 4;
            float4 v = *(const float4*)(Kc + (size_t)(k0 + r) * DHE + c4);
            KVs[(c4 + 0) * 68 + r] = v.x; KVs[(c4 + 1) * 68 + r] = v.y;
            KVs[(c4 + 2) * 68 + r] = v.z; KVs[(c4 + 3) * 68 + r] = v.w;
        }
        __syncthreads();

        float s[4][4];
#pragma unroll
        for (int i = 0; i < 4; i++)
#pragma unroll
            for (int j = 0; j < 4; j++) s[i][j] = 0.f;
#pragma unroll
        for (int d = 0; d < 64; d++) {
            float qr[4], kr[4];
            *(float4*)qr = *(float4*)&Qs[d * 68 + ty * 4];
            *(float4*)kr = *(float4*)&KVs[d * 68 + tx * 4];
#pragma unroll
            for (int i = 0; i < 4; i++)
#pragma unroll
                for (int j = 0; j < 4; j++) s[i][j] = fmaf(qr[i], kr[j], s[i][j]);
        }

        float lg[4][4];
#pragma unroll
        for (int r = 0; r < 4; r++) {
            const int gi = i0 + ty * 4 + r;
            float4 a4 = *(const float4*)(SuA + (size_t)gi * SS + k0 + tx * 4);
            float4 b4 = *(const float4*)(SuB + (size_t)gi * SS + k0 + tx * 4);
            float su[4] = {a4.x + b4.x, a4.y + b4.y, a4.z + b4.z, a4.w + b4.w};
#pragma unroll
            for (int c = 0; c < 4; c++) {
                const int gk = k0 + tx * 4 + c;
                const float x = su[c];
                const float silu = x / (1.f + __expf(-x));
                float v = s[r][c] * SCALE - silu;
                if (gk > gi) v = -1e30f;
                lg[r][c] = v;
            }
        }

#pragma unroll
        for (int r = 0; r < 4; r++) {
            float mx = fmaxf(fmaxf(lg[r][0], lg[r][1]), fmaxf(lg[r][2], lg[r][3]));
#pragma unroll
            for (int off = 1; off < 16; off <<= 1)
                mx = fmaxf(mx, __shfl_xor_sync(0xffffffffu, mx, off));
            const float mnew = fmaxf(m[r], mx);
            const float corr = __expf(m[r] - mnew);
            m[r] = mnew;
            float ps = 0.f;
#pragma unroll
            for (int c = 0; c < 4; c++) {
                const float p = __expf(lg[r][c] - mnew);
                lg[r][c] = p;
                ps += p;
            }
#pragma unroll
            for (int off = 1; off < 16; off <<= 1)
                ps += __shfl_xor_sync(0xffffffffu, ps, off);
            l[r] = l[r] * corr + ps;
#pragma unroll
            for (int c = 0; c < 4; c++) O[r][c] *= corr;
        }

#pragma unroll
        for (int r = 0; r < 4; r++)
#pragma unroll
            for (int c = 0; c < 4; c++)
                Ps[(tx * 4 + c) * 68 + (ty * 4 + r)] = lg[r][c];

        __syncthreads();

        for (int t = tid; t < 64 * 16; t += 256) {
            int r = t >> 4, c4 = (t & 15) * 4;
            *(float4*)&KVs[r * 68 + c4] = *(const float4*)(Vc + (size_t)(k0 + r) * DHE + c4);
        }
        __syncthreads();

#pragma unroll
        for (int kk = 0; kk < 64; kk++) {
            float pr[4], vr[4];
            *(float4*)pr = *(float4*)&Ps[kk * 68 + ty * 4];
            *(float4*)vr = *(float4*)&KVs[kk * 68 + tx * 4];
#pragma unroll
            for (int i = 0; i < 4; i++)
#pragma unroll
                for (int j = 0; j < 4; j++) O[i][j] = fmaf(pr[i], vr[j], O[i][j]);
        }
    }

#pragma unroll
    for (int r = 0; r < 4; r++) {
        const int lr = ty * 4 + r;
        if (tx == 0) {
            g_am[b][chunk][it][lr] = m[r];
            g_al[b][chunk][it][lr] = l[r];
        }
        *(float4*)&g_aO[b][chunk][it][lr * 64 + tx * 4] =
            make_float4(O[r][0], O[r][1], O[r][2], O[r][3]);
    }
}

// ---------------------------------------------------------------------------
// K5: combine split-KV partials (unchanged)
// ---------------------------------------------------------------------------
__global__ void k_comb(float* __restrict__ out) {
    const int it = blockIdx.x, b = blockIdx.y;
    const int nch = it / 8 + 1;
    const int tid = threadIdx.x;
    const int r = tid >> 2;
    const int c0 = (tid & 3) * 16;

    float M = -1e30f;
#pragma unroll
    for (int c = 0; c < 4; c++)
        if (c < nch) M = fmaxf(M, g_am[b][c][it][r]);

    float w[4] = {0.f, 0.f, 0.f, 0.f};
    float lt = 0.f;
#pragma unroll
    for (int c = 0; c < 4; c++)
        if (c < nch) {
            const float wv = __expf(g_am[b][c][it][r] - M);
            w[c] = wv;
            lt += g_al[b][c][it][r] * wv;
        }
    const float inv = 1.f / lt;

    float* dst = out + ((size_t)b * SS + it * 64 + r) * DHE + c0;
#pragma unroll
    for (int j4 = 0; j4 < 4; j4++) {
        float4 acc = make_float4(0.f, 0.f, 0.f, 0.f);
#pragma unroll
        for (int c = 0; c < 4; c++)
            if (c < nch) {
                float4 v = *(const float4*)&g_aO[b][c][it][r * 64 + c0 + j4 * 4];
                acc.x = fmaf(v.x, w[c], acc.x);
                acc.y = fmaf(v.y, w[c], acc.y);
                acc.z = fmaf(v.z, w[c], acc.z);
                acc.w = fmaf(v.w, w[c], acc.w);
            }
        *(float4*)(dst + j4 * 4) =
            make_float4(acc.x * inv, acc.y * inv, acc.z * inv, acc.w * inv);
    }
}

// ---------------------------------------------------------------------------
extern "C" void kernel_launch(void* const* d_in, const int* in_sizes, int n_in,
                              void* d_out, int out_size) {
    const float* x   = (const float*)d_in[0];
    const float* wqu = (const float*)d_in[1];
    const float* wku = (const float*)d_in[2];
    const float* wvu = (const float*)d_in[3];
    const float* wqc = (const float*)d_in[4];
    const float* wkc = (const float*)d_in[5];
    const float* wvc = (const float*)d_in[6];
    float* out = (float*)d_out;

    k_proj<<<dim3(64, 1, 6), 256>>>(x, wqu, wku, wvu, wqc, wkc, wvc);
    k_pair<<<dim3(32, 32, 8), 256>>>();

    const int su_smem = 1024 + 2 * 65536;  // 132096 B
    cudaFuncSetAttribute(k_su_mma, cudaFuncAttributeMaxDynamicSharedMemorySize, su_smem);
    k_su_mma<<<dim3(272, 1, 4), 256, su_smem>>>();

    const int attn_smem = 3 * 64 * 68 * 4;  // 52224 B
    cudaFuncSetAttribute(k_attn_part, cudaFuncAttributeMaxDynamicSharedMemorySize, attn_smem);
    k_attn_part<<<dim3(32, 4, 4), 256, attn_smem>>>();
    k_comb<<<dim3(32, 4), 256>>>(out);
}

// round 6
// speedup vs baseline: 2.5025x; 1.1923x over previous
#include <cuda_runtime.h>
#include <cuda_bf16.h>
#include <cstdint>

#define BB 4
#define SS 2048
#define DD 1024
#define DHE 64
#define SCALE 0.125f

// ---------------- scratch (device globals) ----------------
static __device__ float g_P[6][BB * SS * DHE];  // 0=Qu 1=Ku 2=Vu 3=Qc 4=Kc 5=Vc
static __device__ __nv_bfloat16 g_xh[(size_t)BB * SS * DD];
static __device__ __nv_bfloat16 g_xl[(size_t)BB * SS * DD];
static __device__ __nv_bfloat16 g_wh[6][DHE * DD];  // transposed: [head][n][k]
static __device__ __nv_bfloat16 g_wl[6][DHE * DD];
static __device__ __nv_bfloat16 g_t1h[(size_t)BB * SS * SS];
static __device__ __nv_bfloat16 g_t1l[(size_t)BB * SS * SS];
static __device__ __nv_bfloat16 g_sgh[(size_t)BB * SS * SS];
static __device__ __nv_bfloat16 g_sgl[(size_t)BB * SS * SS];
static __device__ float g_suA[(size_t)BB * SS * SS];
static __device__ float g_suB[(size_t)BB * SS * SS];
static __device__ float g_am[BB][4][32][64];
static __device__ float g_al[BB][4][32][64];
static __device__ float g_aO[BB][4][32][64 * 64];

// ---------------- helpers (compute_103-safe: no 'a' features) ----------------
__device__ __forceinline__ uint32_t smem_to_u32(const void* p) {
    uint32_t a;
    asm("{ .reg .u64 t; cvta.to.shared.u64 t, %1; cvt.u32.u64 %0, t; }" : "=r"(a) : "l"(p));
    return a;
}
#define SW128(o) ((o) ^ (((o) >> 3) & 0x70))

__device__ __forceinline__ void ldsm4(uint32_t* r, uint32_t addr) {
    asm volatile("ldmatrix.sync.aligned.m8n8.x4.shared.b16 {%0,%1,%2,%3}, [%4];"
        : "=r"(r[0]), "=r"(r[1]), "=r"(r[2]), "=r"(r[3]) : "r"(addr));
}
__device__ __forceinline__ void mma16816(float* c, const uint32_t* a,
                                         uint32_t b0, uint32_t b1) {
    asm volatile("mma.sync.aligned.m16n8k16.row.col.f32.bf16.bf16.f32 "
        "{%0,%1,%2,%3}, {%4,%5,%6,%7}, {%8,%9}, {%0,%1,%2,%3};"
        : "+f"(c[0]), "+f"(c[1]), "+f"(c[2]), "+f"(c[3])
        : "r"(a[0]), "r"(a[1]), "r"(a[2]), "r"(a[3]), "r"(b0), "r"(b1));
}

// FFMA-only reciprocal (magic constant + 3 Newton iters, rel err ~1e-8).
// Avoids the MUFU RCP — MUFU is the measured bottleneck in k_pair/k_attn.
__device__ __forceinline__ float fast_rcp(float y) {
    float r = __int_as_float(0x7EF127EAu - __float_as_int(y));
    r = r * fmaf(-y, r, 2.0f);
    r = r * fmaf(-y, r, 2.0f);
    r = r * fmaf(-y, r, 2.0f);
    return r;
}
__device__ __forceinline__ float fast_sigmoid(float x) {
    const float t = __expf(-fmaxf(x, -80.f));   // 1 MUFU (EX2)
    return fast_rcp(1.f + t);                   // FFMA only
}
__device__ __forceinline__ float fast_silu(float x) {
    return x * fast_sigmoid(x);
}

// ---------------------------------------------------------------------------
// K0a: convert x -> bf16 hi/lo
// ---------------------------------------------------------------------------
__global__ void k_cvt_x(const float* __restrict__ x) {
    const size_t n = (size_t)BB * SS * DD;
    for (size_t i = (size_t)blockIdx.x * blockDim.x + threadIdx.x; i < n;
         i += (size_t)gridDim.x * blockDim.x) {
        const float v = x[i];
        const __nv_bfloat16 h = __float2bfloat16(v);
        g_xh[i] = h;
        g_xl[i] = __float2bfloat16(v - __bfloat162float(h));
    }
}
// K0b: convert+transpose weights -> [head][n][k] bf16 hi/lo
__global__ void k_cvt_w(const float* __restrict__ w0, const float* __restrict__ w1,
                        const float* __restrict__ w2, const float* __restrict__ w3,
                        const float* __restrict__ w4, const float* __restrict__ w5) {
    const int n = 6 * DD * DHE;
    for (int i = blockIdx.x * blockDim.x + threadIdx.x; i < n;
         i += gridDim.x * blockDim.x) {
        const int head = i >> 16;          // / (DD*DHE)
        const int rem = i & 65535;
        const int k = rem >> 6, nn = rem & 63;
        const float* w = head == 0 ? w0 : head == 1 ? w1 : head == 2 ? w2
                       : head == 3 ? w3 : head == 4 ? w4 : w5;
        const float v = w[k * DHE + nn];
        const __nv_bfloat16 h = __float2bfloat16(v);
        g_wh[head][nn * DD + k] = h;
        g_wl[head][nn * DD + k] = __float2bfloat16(v - __bfloat162float(h));
    }
}

// ---------------------------------------------------------------------------
// K1: projections via mma.sync bf16 hi/lo (3 products).  out[h] = x @ w[h].
// Per CTA: M=128 rows x N=64, K-chunks of 64, 8 warps (4x2, warp 32x32).
// grid (64 rowtiles, 6 heads), 256 thr, 2-stage double buffer.
// ---------------------------------------------------------------------------
__global__ void __launch_bounds__(256) k_proj_mma() {
    extern __shared__ char smem[];
    const uint32_t tiles = (smem_to_u32(smem) + 1023u) & ~1023u;
    const int row0 = blockIdx.x * 128, head = blockIdx.y;

    const int tid = threadIdx.x;
    const int wid = tid >> 5, lane = tid & 31;
    const int wm = wid & 3, wn = wid >> 2;
    const int lrow = lane & 15;
    const uint32_t kbl = (lane >> 4) * 16;

    // stage layout: Ah 16K | Al 16K | Bh 8K | Bl 8K  (48K/stage)
#define PJ_LOAD(stage, ch) do { \
    const uint32_t _st = tiles + (stage) * 49152; \
    _Pragma("unroll") \
    for (int q = 0; q < 4; q++) { \
        const int r = (tid >> 3) + q * 32; \
        const int c16 = tid & 7; \
        const uint32_t so = SW128((uint32_t)(r * 128 + c16 * 16)); \
        const size_t go = (size_t)(row0 + r) * DD + (ch) + c16 * 8; \
        asm volatile("cp.async.cg.shared.global [%0], [%1], 16;" :: "r"(_st + so), "l"(g_xh + go)); \
        asm volatile("cp.async.cg.shared.global [%0], [%1], 16;" :: "r"(_st + 16384 + so), "l"(g_xl + go)); \
    } \
    _Pragma("unroll") \
    for (int q = 0; q < 2; q++) { \
        const int r = (tid >> 3) + q * 32; \
        const int c16 = tid & 7; \
        const uint32_t so = SW128((uint32_t)(r * 128 + c16 * 16)); \
        const size_t go = (size_t)r * DD + (ch) + c16 * 8; \
        asm volatile("cp.async.cg.shared.global [%0], [%1], 16;" :: "r"(_st + 32768 + so), "l"(g_wh[head] + go)); \
        asm volatile("cp.async.cg.shared.global [%0], [%1], 16;" :: "r"(_st + 40960 + so), "l"(g_wl[head] + go)); \
    } \
    asm volatile("cp.async.commit_group;"); \
} while (0)

    float acc[2][4][4];
#pragma unroll
    for (int mf = 0; mf < 2; mf++)
#pragma unroll
        for (int nf = 0; nf < 4; nf++)
#pragma unroll
            for (int q = 0; q < 4; q++) acc[mf][nf][q] = 0.f;

    PJ_LOAD(0, 0);

    for (int c = 0; c < DD / 64; c++) {
        const int s = c & 1;
        if (c + 1 < DD / 64) {
            PJ_LOAD(s ^ 1, (c + 1) * 64);
            asm volatile("cp.async.wait_group 1;");
        } else {
            asm volatile("cp.async.wait_group 0;");
        }
        __syncthreads();

        const uint32_t stAh = tiles + s * 49152;
        const uint32_t stAl = stAh + 16384;
        const uint32_t stBh = stAh + 32768;
        const uint32_t stBl = stAh + 40960;

#pragma unroll
        for (int ks = 0; ks < 4; ks++) {
            const uint32_t kb = ks * 32 + kbl;
            uint32_t ah[2][4], al[2][4], bh[2][4], bl[2][4];
#pragma unroll
            for (int mf = 0; mf < 2; mf++) {
                const uint32_t off = SW128((uint32_t)((wm * 32 + mf * 16 + lrow) * 128) + kb);
                ldsm4(ah[mf], stAh + off);
                ldsm4(al[mf], stAl + off);
            }
#pragma unroll
            for (int np = 0; np < 2; np++) {
                const uint32_t off = SW128((uint32_t)((wn * 32 + np * 16 + lrow) * 128) + kb);
                ldsm4(bh[np], stBh + off);
                ldsm4(bl[np], stBl + off);
            }
#pragma unroll
            for (int mf = 0; mf < 2; mf++)
#pragma unroll
                for (int nf = 0; nf < 4; nf++) {
                    const int np = nf >> 1, sel = nf & 1;
                    mma16816(acc[mf][nf], ah[mf], bh[np][sel], bh[np][sel + 2]);
                    mma16816(acc[mf][nf], ah[mf], bl[np][sel], bl[np][sel + 2]);
                    mma16816(acc[mf][nf], al[mf], bh[np][sel], bh[np][sel + 2]);
                }
        }
        __syncthreads();
    }
#undef PJ_LOAD

    float* C = g_P[head];
    const int rr = lane >> 2, cc = (lane & 3) * 2;
#pragma unroll
    for (int mf = 0; mf < 2; mf++) {
        const int gr = row0 + wm * 32 + mf * 16 + rr;
#pragma unroll
        for (int nf = 0; nf < 4; nf++) {
            const int gc = wn * 32 + nf * 8 + cc;
            *(float2*)(C + (size_t)gr * DHE + gc) = make_float2(acc[mf][nf][0], acc[mf][nf][1]);
            *(float2*)(C + (size_t)(gr + 8) * DHE + gc) = make_float2(acc[mf][nf][2], acc[mf][nf][3]);
        }
    }
}

// ---------------------------------------------------------------------------
// K2: term1 / sigmoid gate -> bf16 hi/lo pairs.  64x64 tiles, K=64.
// ---------------------------------------------------------------------------
__global__ void k_pair() {
    const int b = blockIdx.z & 3, mode = blockIdx.z >> 2;
    const int it = blockIdx.y, jt = blockIdx.x;
    const int i0 = it * 64, j0 = jt * 64;
    const size_t boff = (size_t)b * SS * SS;
    __nv_bfloat16* outh = (mode == 0 ? g_t1h : g_sgh) + boff;
    __nv_bfloat16* outl = (mode == 0 ? g_t1l : g_sgl) + boff;
    const int tid = threadIdx.x;
    const int tx = tid & 15, ty = tid >> 4;

    const bool skip = (mode == 0) ? (jt > it) : (jt < it);
    if (skip) {
        const bool needed = (mode == 0)
            ? (jt == it + 1 && (it & 1) == 0)
            : (jt == it - 1 && (it & 1) == 1);
        if (!needed) return;
        const uint4 z = make_uint4(0, 0, 0, 0);
        for (int t = tid; t < 64 * 8; t += 256) {
            int r = t >> 3, c8 = (t & 7) * 8;
            *(uint4*)(outh + (size_t)(i0 + r) * SS + j0 + c8) = z;
            *(uint4*)(outl + (size_t)(i0 + r) * SS + j0 + c8) = z;
        }
        return;
    }

    const float* A  = g_P[mode == 0 ? 3 : 0] + (size_t)b * SS * DHE;  // Qc | Qu
    const float* Bm = g_P[mode == 0 ? 2 : 1] + (size_t)b * SS * DHE;  // Vu | Ku

    __shared__ float As[64][68];
    __shared__ float Bs[64][68];

    for (int t = tid; t < 64 * 16; t += 256) {
        int r = t >> 4, c4 = (t & 15) * 4;
        float4 va = *(const float4*)(A + (size_t)(i0 + r) * DHE + c4);
        As[c4 + 0][r] = va.x; As[c4 + 1][r] = va.y; As[c4 + 2][r] = va.z; As[c4 + 3][r] = va.w;
        float4 vb = *(const float4*)(Bm + (size_t)(j0 + r) * DHE + c4);
        Bs[c4 + 0][r] = vb.x; Bs[c4 + 1][r] = vb.y; Bs[c4 + 2][r] = vb.z; Bs[c4 + 3][r] = vb.w;
    }
    __syncthreads();

    float acc[4][4];
#pragma unroll
    for (int i = 0; i < 4; i++)
#pragma unroll
        for (int j = 0; j < 4; j++) acc[i][j] = 0.f;

#pragma unroll
    for (int d = 0; d < 64; d++) {
        float ar[4], br[4];
        *(float4*)ar = *(float4*)&As[d][ty * 4];
        *(float4*)br = *(float4*)&Bs[d][tx * 4];
#pragma unroll
        for (int i = 0; i < 4; i++)
#pragma unroll
            for (int j = 0; j < 4; j++) acc[i][j] = fmaf(ar[i], br[j], acc[i][j]);
    }

#pragma unroll
    for (int r = 0; r < 4; r++) {
        const int gi = i0 + ty * 4 + r;
        union { __nv_bfloat162 b2[2]; uint2 u; } hu, lu;
#pragma unroll
        for (int c2 = 0; c2 < 2; c2++) {
            __nv_bfloat16 hh[2], ll[2];
#pragma unroll
            for (int q = 0; q < 2; q++) {
                const int c = c2 * 2 + q;
                const int gj = j0 + tx * 4 + c;
                float v = acc[r][c] * SCALE;
                if (mode == 0) {
                    v = (gj <= gi) ? v : 0.f;
                } else {
                    v = (gj > gi) ? fast_sigmoid(v) : 0.f;
                }
                hh[q] = __float2bfloat16(v);
                ll[q] = __float2bfloat16(v - __bfloat162float(hh[q]));
            }
            hu.b2[c2] = __halves2bfloat162(hh[0], hh[1]);
            lu.b2[c2] = __halves2bfloat162(ll[0], ll[1]);
        }
        *(uint2*)(outh + (size_t)gi * SS + j0 + tx * 4) = hu.u;
        *(uint2*)(outl + (size_t)gi * SS + j0 + tx * 4) = lu.u;
    }
}

// ---------------------------------------------------------------------------
// K3: S_u via mma.sync bf16x2-split (unchanged from R4)
// ---------------------------------------------------------------------------
__global__ void __launch_bounds__(256) k_su_mma() {
    extern __shared__ char smem[];
    const uint32_t tiles = (smem_to_u32(smem) + 1023u) & ~1023u;

    const int b = blockIdx.z;
    const int seg = blockIdx.x & 1;
    int pp = blockIdx.x >> 1;
    int d = 15;
    while (pp >= 16 - d) { pp -= 16 - d; d--; }
    const int kt = pp, it = pp + d;
    const int i0 = it * 128, k0 = kt * 128;

    int jbeg = k0, jend = (it + 1) * 128;
    const int mid = jbeg + ((jend - jbeg) >> 1);
    if (seg == 0) jend = mid; else jbeg = mid;
    const int nch = (jend - jbeg) >> 6;

    const int tid = threadIdx.x;
    const int wid = tid >> 5, lane = tid & 31;

    const int ltile = tid >> 6;
    const int llane = tid & 63;
    const int rl = llane >> 3;
    const int c16 = llane & 7;
    const size_t boff = (size_t)b * SS * SS;
    const __nv_bfloat16* src =
        (ltile == 0) ? g_t1h + boff + (size_t)i0 * SS :
        (ltile == 1) ? g_t1l + boff + (size_t)i0 * SS :
        (ltile == 2) ? g_sgh + boff + (size_t)k0 * SS :
                       g_sgl + boff + (size_t)k0 * SS;
    const __nv_bfloat16* gbase = src + (size_t)rl * SS + c16 * 8;
    const uint32_t tsm = tiles + ltile * 16384;

#define SU_LOAD_CHUNK(stage, j0v) do { \
    const __nv_bfloat16* _g = gbase + (j0v); \
    const uint32_t _base = tsm + (stage) * 65536; \
    _Pragma("unroll") \
    for (int q = 0; q < 16; q++) { \
        uint32_t so = (uint32_t)((q * 8 + rl) * 128 + c16 * 16); \
        uint32_t sa = _base + SW128(so); \
        asm volatile("cp.async.cg.shared.global [%0], [%1], 16;" :: "r"(sa), "l"(_g + (size_t)q * 8 * SS)); \
    } \
    asm volatile("cp.async.commit_group;"); \
} while (0)

    float acc[2][8][4];
#pragma unroll
    for (int mf = 0; mf < 2; mf++)
#pragma unroll
        for (int nf = 0; nf < 8; nf++)
#pragma unroll
            for (int q = 0; q < 4; q++) acc[mf][nf][q] = 0.f;

    const int wm = wid >> 1, wn = wid & 1;
    const int lrow = lane & 15;
    const uint32_t kbl = (lane >> 4) * 16;

    SU_LOAD_CHUNK(0, jbeg);

    for (int i = 0; i < nch; i++) {
        const int s = i & 1;
        if (i + 1 < nch) {
            SU_LOAD_CHUNK(s ^ 1, jbeg + (i + 1) * 64);
            asm volatile("cp.async.wait_group 1;");
        } else {
            asm volatile("cp.async.wait_group 0;");
        }
        __syncthreads();

        const uint32_t stAh = tiles + s * 65536;
        const uint32_t stAl = stAh + 16384;
        const uint32_t stBh = stAh + 32768;
        const uint32_t stBl = stAh + 49152;

#pragma unroll
        for (int ks = 0; ks < 4; ks++) {
            const uint32_t kb = ks * 32 + kbl;
            uint32_t ah[2][4], al[2][4], bh[4][4], bl[4][4];
#pragma unroll
            for (int mf = 0; mf < 2; mf++) {
                const uint32_t off = SW128((uint32_t)((wm * 32 + mf * 16 + lrow) * 128) + kb);
                ldsm4(ah[mf], stAh + off);
                ldsm4(al[mf], stAl + off);
            }
#pragma unroll
            for (int np = 0; np < 4; np++) {
                const uint32_t off = SW128((uint32_t)((wn * 64 + np * 16 + lrow) * 128) + kb);
                ldsm4(bh[np], stBh + off);
                ldsm4(bl[np], stBl + off);
            }
#pragma unroll
            for (int mf = 0; mf < 2; mf++)
#pragma unroll
                for (int nf = 0; nf < 8; nf++) {
                    const int np = nf >> 1, sel = nf & 1;
                    mma16816(acc[mf][nf], ah[mf], bh[np][sel], bh[np][sel + 2]);
                    mma16816(acc[mf][nf], ah[mf], bl[np][sel], bl[np][sel + 2]);
                    mma16816(acc[mf][nf], al[mf], bh[np][sel], bh[np][sel + 2]);
                }
        }
        __syncthreads();
    }
#undef SU_LOAD_CHUNK

    float* C = (seg ? g_suB : g_suA) + boff;
    const int rr = lane >> 2, cc = (lane & 3) * 2;
#pragma unroll
    for (int mf = 0; mf < 2; mf++) {
        const int gr = i0 + wm * 32 + mf * 16 + rr;
#pragma unroll
        for (int nf = 0; nf < 8; nf++) {
            const int gc = k0 + wn * 64 + nf * 8 + cc;
            *(float2*)(C + (size_t)gr * SS + gc) = make_float2(acc[mf][nf][0], acc[mf][nf][1]);
            *(float2*)(C + (size_t)(gr + 8) * SS + gc) = make_float2(acc[mf][nf][2], acc[mf][nf][3]);
        }
    }
}

// ---------------------------------------------------------------------------
// K4: split-KV flash attention partial (silu via fast_rcp; rest unchanged)
// ---------------------------------------------------------------------------
__global__ void __launch_bounds__(256) k_attn_part() {
    const int it = blockIdx.x, chunk = blockIdx.y, b = blockIdx.z;
    if (chunk * 8 > it) return;
    const int kt_beg = chunk * 8;
    const int kt_end = min(kt_beg + 8, it + 1);
    const int i0 = it * 64;

    extern __shared__ float sm[];
    float* Qs  = sm;
    float* KVs = sm + 64 * 68;
    float* Ps  = sm + 2 * 64 * 68;

    const float* Qc  = g_P[3] + (size_t)b * SS * DHE;
    const float* Kc  = g_P[4] + (size_t)b * SS * DHE;
    const float* Vc  = g_P[5] + (size_t)b * SS * DHE;
    const float* SuA = g_suA + (size_t)b * SS * SS;
    const float* SuB = g_suB + (size_t)b * SS * SS;

    const int tid = threadIdx.x;
    const int tx = tid & 15, ty = tid >> 4;

    for (int t = tid; t < 64 * 16; t += 256) {
        int r = t >> 4, c4 = (t & 15) * 4;
        float4 v = *(const float4*)(Qc + (size_t)(i0 + r) * DHE + c4);
        Qs[(c4 + 0) * 68 + r] = v.x; Qs[(c4 + 1) * 68 + r] = v.y;
        Qs[(c4 + 2) * 68 + r] = v.z; Qs[(c4 + 3) * 68 + r] = v.w;
    }

    float m[4], l[4], O[4][4];
#pragma unroll
    for (int r = 0; r < 4; r++) {
        m[r] = -1e30f; l[r] = 0.f;
#pragma unroll
        for (int c = 0; c < 4; c++) O[r][c] = 0.f;
    }

    for (int kt = kt_beg; kt < kt_end; kt++) {
        const int k0 = kt * 64;
        __syncthreads();
        for (int t = tid; t < 64 * 16; t += 256) {
            int r = t >> 4, c4 = (t & 15) * 4;
            float4 v = *(const float4*)(Kc + (size_t)(k0 + r) * DHE + c4);
            KVs[(c4 + 0) * 68 + r] = v.x; KVs[(c4 + 1) * 68 + r] = v.y;
            KVs[(c4 + 2) * 68 + r] = v.z; KVs[(c4 + 3) * 68 + r] = v.w;
        }
        __syncthreads();

        float s[4][4];
#pragma unroll
        for (int i = 0; i < 4; i++)
#pragma unroll
            for (int j = 0; j < 4; j++) s[i][j] = 0.f;
#pragma unroll
        for (int d = 0; d < 64; d++) {
            float qr[4], kr[4];
            *(float4*)qr = *(float4*)&Qs[d * 68 + ty * 4];
            *(float4*)kr = *(float4*)&KVs[d * 68 + tx * 4];
#pragma unroll
            for (int i = 0; i < 4; i++)
#pragma unroll
                for (int j = 0; j < 4; j++) s[i][j] = fmaf(qr[i], kr[j], s[i][j]);
        }

        float lg[4][4];
#pragma unroll
        for (int r = 0; r < 4; r++) {
            const int gi = i0 + ty * 4 + r;
            float4 a4 = *(const float4*)(SuA + (size_t)gi * SS + k0 + tx * 4);
            float4 b4 = *(const float4*)(SuB + (size_t)gi * SS + k0 + tx * 4);
            float su[4] = {a4.x + b4.x, a4.y + b4.y, a4.z + b4.z, a4.w + b4.w};
#pragma unroll
            for (int c = 0; c < 4; c++) {
                const int gk = k0 + tx * 4 + c;
                float v = s[r][c] * SCALE - fast_silu(su[c]);
                if (gk > gi) v = -1e30f;
                lg[r][c] = v;
            }
        }

#pragma unroll
        for (int r = 0; r < 4; r++) {
            float mx = fmaxf(fmaxf(lg[r][0], lg[r][1]), fmaxf(lg[r][2], lg[r][3]));
#pragma unroll
            for (int off = 1; off < 16; off <<= 1)
                mx = fmaxf(mx, __shfl_xor_sync(0xffffffffu, mx, off));
            const float mnew = fmaxf(m[r], mx);
            const float corr = __expf(m[r] - mnew);
            m[r] = mnew;
            float ps = 0.f;
#pragma unroll
            for (int c = 0; c < 4; c++) {
                const float p = __expf(lg[r][c] - mnew);
                lg[r][c] = p;
                ps += p;
            }
#pragma unroll
            for (int off = 1; off < 16; off <<= 1)
                ps += __shfl_xor_sync(0xffffffffu, ps, off);
            l[r] = l[r] * corr + ps;
#pragma unroll
            for (int c = 0; c < 4; c++) O[r][c] *= corr;
        }

#pragma unroll
        for (int r = 0; r < 4; r++)
#pragma unroll
            for (int c = 0; c < 4; c++)
                Ps[(tx * 4 + c) * 68 + (ty * 4 + r)] = lg[r][c];

        __syncthreads();

        for (int t = tid; t < 64 * 16; t += 256) {
            int r = t >> 4, c4 = (t & 15) * 4;
            *(float4*)&KVs[r * 68 + c4] = *(const float4*)(Vc + (size_t)(k0 + r) * DHE + c4);
        }
        __syncthreads();

#pragma unroll
        for (int kk = 0; kk < 64; kk++) {
            float pr[4], vr[4];
            *(float4*)pr = *(float4*)&Ps[kk * 68 + ty * 4];
            *(float4*)vr = *(float4*)&KVs[kk * 68 + tx * 4];
#pragma unroll
            for (int i = 0; i < 4; i++)
#pragma unroll
                for (int j = 0; j < 4; j++) O[i][j] = fmaf(pr[i], vr[j], O[i][j]);
        }
    }

#pragma unroll
    for (int r = 0; r < 4; r++) {
        const int lr = ty * 4 + r;
        if (tx == 0) {
            g_am[b][chunk][it][lr] = m[r];
            g_al[b][chunk][it][lr] = l[r];
        }
        *(float4*)&g_aO[b][chunk][it][lr * 64 + tx * 4] =
            make_float4(O[r][0], O[r][1], O[r][2], O[r][3]);
    }
}

// ---------------------------------------------------------------------------
// K5: combine split-KV partials (unchanged)
// ---------------------------------------------------------------------------
__global__ void k_comb(float* __restrict__ out) {
    const int it = blockIdx.x, b = blockIdx.y;
    const int nch = it / 8 + 1;
    const int tid = threadIdx.x;
    const int r = tid >> 2;
    const int c0 = (tid & 3) * 16;

    float M = -1e30f;
#pragma unroll
    for (int c = 0; c < 4; c++)
        if (c < nch) M = fmaxf(M, g_am[b][c][it][r]);

    float w[4] = {0.f, 0.f, 0.f, 0.f};
    float lt = 0.f;
#pragma unroll
    for (int c = 0; c < 4; c++)
        if (c < nch) {
            const float wv = __expf(g_am[b][c][it][r] - M);
            w[c] = wv;
            lt += g_al[b][c][it][r] * wv;
        }
    const float inv = 1.f / lt;

    float* dst = out + ((size_t)b * SS + it * 64 + r) * DHE + c0;
#pragma unroll
    for (int j4 = 0; j4 < 4; j4++) {
        float4 acc = make_float4(0.f, 0.f, 0.f, 0.f);
#pragma unroll
        for (int c = 0; c < 4; c++)
            if (c < nch) {
                float4 v = *(const float4*)&g_aO[b][c][it][r * 64 + c0 + j4 * 4];
                acc.x = fmaf(v.x, w[c], acc.x);
                acc.y = fmaf(v.y, w[c], acc.y);
                acc.z = fmaf(v.z, w[c], acc.z);
                acc.w = fmaf(v.w, w[c], acc.w);
            }
        *(float4*)(dst + j4 * 4) =
            make_float4(acc.x * inv, acc.y * inv, acc.z * inv, acc.w * inv);
    }
}

// ---------------------------------------------------------------------------
extern "C" void kernel_launch(void* const* d_in, const int* in_sizes, int n_in,
                              void* d_out, int out_size) {
    const float* x   = (const float*)d_in[0];
    const float* wqu = (const float*)d_in[1];
    const float* wku = (const float*)d_in[2];
    const float* wvu = (const float*)d_in[3];
    const float* wqc = (const float*)d_in[4];
    const float* wkc = (const float*)d_in[5];
    const float* wvc = (const float*)d_in[6];
    float* out = (float*)d_out;

    k_cvt_x<<<2048, 256>>>(x);
    k_cvt_w<<<192, 256>>>(wqu, wku, wvu, wqc, wkc, wvc);

    const int proj_smem = 1024 + 2 * 49152;  // 99328 B
    cudaFuncSetAttribute(k_proj_mma, cudaFuncAttributeMaxDynamicSharedMemorySize, proj_smem);
    k_proj_mma<<<dim3(64, 6), 256, proj_smem>>>();

    k_pair<<<dim3(32, 32, 8), 256>>>();

    const int su_smem = 1024 + 2 * 65536;  // 132096 B
    cudaFuncSetAttribute(k_su_mma, cudaFuncAttributeMaxDynamicSharedMemorySize, su_smem);
    k_su_mma<<<dim3(272, 1, 4), 256, su_smem>>>();

    const int attn_smem = 3 * 64 * 68 * 4;  // 52224 B
    cudaFuncSetAttribute(k_attn_part, cudaFuncAttributeMaxDynamicSharedMemorySize, attn_smem);
    k_attn_part<<<dim3(32, 4, 4), 256, attn_smem>>>();
    k_comb<<<dim3(32, 4), 256>>>(out);
}

// round 7
// speedup vs baseline: 2.8213x; 1.1274x over previous
#include <cuda_runtime.h>
#include <cuda_bf16.h>
#include <cstdint>

#define BB 4
#define SS 2048
#define DD 1024
#define DHE 64
#define SCALE 0.125f

// ---------------- scratch (device globals) ----------------
static __device__ float g_P[6][BB * SS * DHE];  // 0=Qu 1=Ku 2=Vu 3=Qc 4=Kc 5=Vc
static __device__ __nv_bfloat16 g_Ph[4][BB * SS * DHE];  // hi of Qu,Ku,Vu,Qc
static __device__ __nv_bfloat16 g_Pl[4][BB * SS * DHE];  // lo
static __device__ __nv_bfloat16 g_xh[(size_t)BB * SS * DD];
static __device__ __nv_bfloat16 g_xl[(size_t)BB * SS * DD];
static __device__ __nv_bfloat16 g_wh[6][DHE * DD];  // transposed: [head][n][k]
static __device__ __nv_bfloat16 g_wl[6][DHE * DD];
static __device__ __nv_bfloat16 g_t1h[(size_t)BB * SS * SS];
static __device__ __nv_bfloat16 g_t1l[(size_t)BB * SS * SS];
static __device__ __nv_bfloat16 g_sgh[(size_t)BB * SS * SS];
static __device__ __nv_bfloat16 g_sgl[(size_t)BB * SS * SS];
static __device__ float g_suA[(size_t)BB * SS * SS];
static __device__ float g_suB[(size_t)BB * SS * SS];
static __device__ float g_am[BB][4][32][64];
static __device__ float g_al[BB][4][32][64];
static __device__ float g_aO[BB][4][32][64 * 64];

// ---------------- helpers (compute_103-safe: no 'a' features) ----------------
__device__ __forceinline__ uint32_t smem_to_u32(const void* p) {
    uint32_t a;
    asm("{ .reg .u64 t; cvta.to.shared.u64 t, %1; cvt.u32.u64 %0, t; }" : "=r"(a) : "l"(p));
    return a;
}
#define SW128(o) ((o) ^ (((o) >> 3) & 0x70))

__device__ __forceinline__ void ldsm4(uint32_t* r, uint32_t addr) {
    asm volatile("ldmatrix.sync.aligned.m8n8.x4.shared.b16 {%0,%1,%2,%3}, [%4];"
        : "=r"(r[0]), "=r"(r[1]), "=r"(r[2]), "=r"(r[3]) : "r"(addr));
}
__device__ __forceinline__ void mma16816(float* c, const uint32_t* a,
                                         uint32_t b0, uint32_t b1) {
    asm volatile("mma.sync.aligned.m16n8k16.row.col.f32.bf16.bf16.f32 "
        "{%0,%1,%2,%3}, {%4,%5,%6,%7}, {%8,%9}, {%0,%1,%2,%3};"
        : "+f"(c[0]), "+f"(c[1]), "+f"(c[2]), "+f"(c[3])
        : "r"(a[0]), "r"(a[1]), "r"(a[2]), "r"(a[3]), "r"(b0), "r"(b1));
}

__device__ __forceinline__ float fast_rcp(float y) {
    float r = __int_as_float(0x7EF127EAu - __float_as_int(y));
    r = r * fmaf(-y, r, 2.0f);
    r = r * fmaf(-y, r, 2.0f);
    r = r * fmaf(-y, r, 2.0f);
    return r;
}
__device__ __forceinline__ float fast_sigmoid(float x) {
    const float t = __expf(-fmaxf(x, -80.f));
    return fast_rcp(1.f + t);
}
__device__ __forceinline__ float fast_silu(float x) {
    return x * fast_sigmoid(x);
}
// split two floats into packed bf16x2 hi / lo words
__device__ __forceinline__ void split2(float v0, float v1, uint32_t& h, uint32_t& l) {
    const __nv_bfloat16 h0 = __float2bfloat16(v0), h1 = __float2bfloat16(v1);
    const __nv_bfloat16 l0 = __float2bfloat16(v0 - __bfloat162float(h0));
    const __nv_bfloat16 l1 = __float2bfloat16(v1 - __bfloat162float(h1));
    union { __nv_bfloat162 b; uint32_t u; } H, L;
    H.b = __halves2bfloat162(h0, h1);
    L.b = __halves2bfloat162(l0, l1);
    h = H.u; l = L.u;
}

// ---------------------------------------------------------------------------
// K0a: convert x -> bf16 hi/lo
// ---------------------------------------------------------------------------
__global__ void k_cvt_x(const float* __restrict__ x) {
    const size_t n = (size_t)BB * SS * DD;
    for (size_t i = (size_t)blockIdx.x * blockDim.x + threadIdx.x; i < n;
         i += (size_t)gridDim.x * blockDim.x) {
        const float v = x[i];
        const __nv_bfloat16 h = __float2bfloat16(v);
        g_xh[i] = h;
        g_xl[i] = __float2bfloat16(v - __bfloat162float(h));
    }
}
// K0b: convert+transpose weights -> [head][n][k] bf16 hi/lo
__global__ void k_cvt_w(const float* __restrict__ w0, const float* __restrict__ w1,
                        const float* __restrict__ w2, const float* __restrict__ w3,
                        const float* __restrict__ w4, const float* __restrict__ w5) {
    const int n = 6 * DD * DHE;
    for (int i = blockIdx.x * blockDim.x + threadIdx.x; i < n;
         i += gridDim.x * blockDim.x) {
        const int head = i >> 16;
        const int rem = i & 65535;
        const int k = rem >> 6, nn = rem & 63;
        const float* w = head == 0 ? w0 : head == 1 ? w1 : head == 2 ? w2
                       : head == 3 ? w3 : head == 4 ? w4 : w5;
        const float v = w[k * DHE + nn];
        const __nv_bfloat16 h = __float2bfloat16(v);
        g_wh[head][nn * DD + k] = h;
        g_wl[head][nn * DD + k] = __float2bfloat16(v - __bfloat162float(h));
    }
}

// ---------------------------------------------------------------------------
// K1: projections via mma.sync bf16 hi/lo.  out[h] = x @ w[h].
// Also emits bf16 hi/lo copies for heads 0..3 (pair-GEMM operands).
// ---------------------------------------------------------------------------
__global__ void __launch_bounds__(256) k_proj_mma() {
    extern __shared__ char smem[];
    const uint32_t tiles = (smem_to_u32(smem) + 1023u) & ~1023u;
    const int row0 = blockIdx.x * 128, head = blockIdx.y;

    const int tid = threadIdx.x;
    const int wid = tid >> 5, lane = tid & 31;
    const int wm = wid & 3, wn = wid >> 2;
    const int lrow = lane & 15;
    const uint32_t kbl = (lane >> 4) * 16;

#define PJ_LOAD(stage, ch) do { \
    const uint32_t _st = tiles + (stage) * 49152; \
    _Pragma("unroll") \
    for (int q = 0; q < 4; q++) { \
        const int r = (tid >> 3) + q * 32; \
        const int c16 = tid & 7; \
        const uint32_t so = SW128((uint32_t)(r * 128 + c16 * 16)); \
        const size_t go = (size_t)(row0 + r) * DD + (ch) + c16 * 8; \
        asm volatile("cp.async.cg.shared.global [%0], [%1], 16;" :: "r"(_st + so), "l"(g_xh + go)); \
        asm volatile("cp.async.cg.shared.global [%0], [%1], 16;" :: "r"(_st + 16384 + so), "l"(g_xl + go)); \
    } \
    _Pragma("unroll") \
    for (int q = 0; q < 2; q++) { \
        const int r = (tid >> 3) + q * 32; \
        const int c16 = tid & 7; \
        const uint32_t so = SW128((uint32_t)(r * 128 + c16 * 16)); \
        const size_t go = (size_t)r * DD + (ch) + c16 * 8; \
        asm volatile("cp.async.cg.shared.global [%0], [%1], 16;" :: "r"(_st + 32768 + so), "l"(g_wh[head] + go)); \
        asm volatile("cp.async.cg.shared.global [%0], [%1], 16;" :: "r"(_st + 40960 + so), "l"(g_wl[head] + go)); \
    } \
    asm volatile("cp.async.commit_group;"); \
} while (0)

    float acc[2][4][4];
#pragma unroll
    for (int mf = 0; mf < 2; mf++)
#pragma unroll
        for (int nf = 0; nf < 4; nf++)
#pragma unroll
            for (int q = 0; q < 4; q++) acc[mf][nf][q] = 0.f;

    PJ_LOAD(0, 0);

    for (int c = 0; c < DD / 64; c++) {
        const int s = c & 1;
        if (c + 1 < DD / 64) {
            PJ_LOAD(s ^ 1, (c + 1) * 64);
            asm volatile("cp.async.wait_group 1;");
        } else {
            asm volatile("cp.async.wait_group 0;");
        }
        __syncthreads();

        const uint32_t stAh = tiles + s * 49152;
        const uint32_t stAl = stAh + 16384;
        const uint32_t stBh = stAh + 32768;
        const uint32_t stBl = stAh + 40960;

#pragma unroll
        for (int ks = 0; ks < 4; ks++) {
            const uint32_t kb = ks * 32 + kbl;
            uint32_t ah[2][4], al[2][4], bh[2][4], bl[2][4];
#pragma unroll
            for (int mf = 0; mf < 2; mf++) {
                const uint32_t off = SW128((uint32_t)((wm * 32 + mf * 16 + lrow) * 128) + kb);
                ldsm4(ah[mf], stAh + off);
                ldsm4(al[mf], stAl + off);
            }
#pragma unroll
            for (int np = 0; np < 2; np++) {
                const uint32_t off = SW128((uint32_t)((wn * 32 + np * 16 + lrow) * 128) + kb);
                ldsm4(bh[np], stBh + off);
                ldsm4(bl[np], stBl + off);
            }
#pragma unroll
            for (int mf = 0; mf < 2; mf++)
#pragma unroll
                for (int nf = 0; nf < 4; nf++) {
                    const int np = nf >> 1, sel = nf & 1;
                    mma16816(acc[mf][nf], ah[mf], bh[np][sel], bh[np][sel + 2]);
                    mma16816(acc[mf][nf], ah[mf], bl[np][sel], bl[np][sel + 2]);
                    mma16816(acc[mf][nf], al[mf], bh[np][sel], bh[np][sel + 2]);
                }
        }
        __syncthreads();
    }
#undef PJ_LOAD

    float* C = g_P[head];
    const int rr = lane >> 2, cc = (lane & 3) * 2;
#pragma unroll
    for (int mf = 0; mf < 2; mf++) {
        const int gr = row0 + wm * 32 + mf * 16 + rr;
#pragma unroll
        for (int nf = 0; nf < 4; nf++) {
            const int gc = wn * 32 + nf * 8 + cc;
            *(float2*)(C + (size_t)gr * DHE + gc) = make_float2(acc[mf][nf][0], acc[mf][nf][1]);
            *(float2*)(C + (size_t)(gr + 8) * DHE + gc) = make_float2(acc[mf][nf][2], acc[mf][nf][3]);
        }
    }
    if (head < 4) {
        __nv_bfloat16* Hh = g_Ph[head];
        __nv_bfloat16* Hl = g_Pl[head];
#pragma unroll
        for (int mf = 0; mf < 2; mf++) {
            const int gr = row0 + wm * 32 + mf * 16 + rr;
#pragma unroll
            for (int nf = 0; nf < 4; nf++) {
                const int gc = wn * 32 + nf * 8 + cc;
                uint32_t h0, l0, h1, l1;
                split2(acc[mf][nf][0], acc[mf][nf][1], h0, l0);
                split2(acc[mf][nf][2], acc[mf][nf][3], h1, l1);
                *(uint32_t*)(Hh + (size_t)gr * DHE + gc) = h0;
                *(uint32_t*)(Hl + (size_t)gr * DHE + gc) = l0;
                *(uint32_t*)(Hh + (size_t)(gr + 8) * DHE + gc) = h1;
                *(uint32_t*)(Hl + (size_t)(gr + 8) * DHE + gc) = l1;
            }
        }
    }
}

// ---------------------------------------------------------------------------
// K2: term1 (mode 0) / sigmoid gate (mode 1) via mma.sync, 128x128 tiles.
// A = Qc|Qu hi/lo, B = Vu|Ku hi/lo, K=64 single chunk, 3 products.
// Masked zeros land inside diagonal tiles -> no separate fill tiles.
// grid (136 tri-pairs, 4 b, 2 modes), 256 thr, 66560 B smem.
// ---------------------------------------------------------------------------
__global__ void __launch_bounds__(256) k_pair_mma() {
    extern __shared__ char smem[];
    const uint32_t tiles = (smem_to_u32(smem) + 1023u) & ~1023u;

    const int mode = blockIdx.z, b = blockIdx.y;
    int pp = blockIdx.x;
    int d = 15;
    while (pp >= 16 - d) { pp -= 16 - d; d--; }
    // mode0 (term1): rows it = pp+d, cols jt = pp  (lower tri incl diag)
    // mode1 (sig):   rows kt = pp,   cols jt = pp+d (upper tri incl diag)
    const int rt = (mode == 0) ? (pp + d) : pp;
    const int ct = (mode == 0) ? pp : (pp + d);
    const int i0 = rt * 128, j0 = ct * 128;
    const int hA = (mode == 0) ? 3 : 0;  // Qc | Qu
    const int hB = (mode == 0) ? 2 : 1;  // Vu | Ku

    const int tid = threadIdx.x;
    const int wid = tid >> 5, lane = tid & 31;

    // load 4 tiles of 128 rows x 128B: Ah Al Bh Bl
    {
        const int ltile = tid >> 6;
        const int llane = tid & 63;
        const int rl = llane >> 3, c16 = llane & 7;
        const __nv_bfloat16* src =
            (ltile == 0) ? g_Ph[hA] + ((size_t)b * SS + i0) * DHE :
            (ltile == 1) ? g_Pl[hA] + ((size_t)b * SS + i0) * DHE :
            (ltile == 2) ? g_Ph[hB] + ((size_t)b * SS + j0) * DHE :
                           g_Pl[hB] + ((size_t)b * SS + j0) * DHE;
        const __nv_bfloat16* g = src + (size_t)rl * DHE + c16 * 8;
        const uint32_t tsm = tiles + ltile * 16384;
#pragma unroll
        for (int q = 0; q < 16; q++) {
            const uint32_t so = SW128((uint32_t)((q * 8 + rl) * 128 + c16 * 16));
            asm volatile("cp.async.cg.shared.global [%0], [%1], 16;"
                :: "r"(tsm + so), "l"(g + (size_t)q * 8 * DHE));
        }
        asm volatile("cp.async.commit_group;");
        asm volatile("cp.async.wait_group 0;");
    }
    __syncthreads();

    float acc[2][8][4];
#pragma unroll
    for (int mf = 0; mf < 2; mf++)
#pragma unroll
        for (int nf = 0; nf < 8; nf++)
#pragma unroll
            for (int q = 0; q < 4; q++) acc[mf][nf][q] = 0.f;

    const int wm = wid >> 1, wn = wid & 1;
    const int lrow = lane & 15;
    const uint32_t kbl = (lane >> 4) * 16;
    const uint32_t stAh = tiles, stAl = tiles + 16384;
    const uint32_t stBh = tiles + 32768, stBl = tiles + 49152;

#pragma unroll
    for (int ks = 0; ks < 4; ks++) {
        const uint32_t kb = ks * 32 + kbl;
        uint32_t ah[2][4], al[2][4], bh[4][4], bl[4][4];
#pragma unroll
        for (int mf = 0; mf < 2; mf++) {
            const uint32_t off = SW128((uint32_t)((wm * 32 + mf * 16 + lrow) * 128) + kb);
            ldsm4(ah[mf], stAh + off);
            ldsm4(al[mf], stAl + off);
        }
#pragma unroll
        for (int np = 0; np < 4; np++) {
            const uint32_t off = SW128((uint32_t)((wn * 64 + np * 16 + lrow) * 128) + kb);
            ldsm4(bh[np], stBh + off);
            ldsm4(bl[np], stBl + off);
        }
#pragma unroll
        for (int mf = 0; mf < 2; mf++)
#pragma unroll
            for (int nf = 0; nf < 8; nf++) {
                const int np = nf >> 1, sel = nf & 1;
                mma16816(acc[mf][nf], ah[mf], bh[np][sel], bh[np][sel + 2]);
                mma16816(acc[mf][nf], ah[mf], bl[np][sel], bl[np][sel + 2]);
                mma16816(acc[mf][nf], al[mf], bh[np][sel], bh[np][sel + 2]);
            }
    }

    const size_t boff = (size_t)b * SS * SS;
    __nv_bfloat16* outh = (mode == 0 ? g_t1h : g_sgh) + boff;
    __nv_bfloat16* outl = (mode == 0 ? g_t1l : g_sgl) + boff;
    const int rr = lane >> 2, cc = (lane & 3) * 2;
#pragma unroll
    for (int mf = 0; mf < 2; mf++) {
#pragma unroll
        for (int half = 0; half < 2; half++) {
            const int gi = i0 + wm * 32 + mf * 16 + half * 8 + rr;
#pragma unroll
            for (int nf = 0; nf < 8; nf++) {
                const int gc = j0 + wn * 64 + nf * 8 + cc;
                float v0 = acc[mf][nf][half * 2 + 0] * SCALE;
                float v1 = acc[mf][nf][half * 2 + 1] * SCALE;
                if (mode == 0) {
                    v0 = (gc <= gi) ? v0 : 0.f;
                    v1 = (gc + 1 <= gi) ? v1 : 0.f;
                } else {
                    v0 = (gc > gi) ? fast_sigmoid(v0) : 0.f;
                    v1 = (gc + 1 > gi) ? fast_sigmoid(v1) : 0.f;
                }
                uint32_t h, l;
                split2(v0, v1, h, l);
                *(uint32_t*)(outh + (size_t)gi * SS + gc) = h;
                *(uint32_t*)(outl + (size_t)gi * SS + gc) = l;
            }
        }
    }
}

// ---------------------------------------------------------------------------
// K3: S_u via mma.sync bf16x2-split (unchanged)
// ---------------------------------------------------------------------------
__global__ void __launch_bounds__(256) k_su_mma() {
    extern __shared__ char smem[];
    const uint32_t tiles = (smem_to_u32(smem) + 1023u) & ~1023u;

    const int b = blockIdx.z;
    const int seg = blockIdx.x & 1;
    int pp = blockIdx.x >> 1;
    int d = 15;
    while (pp >= 16 - d) { pp -= 16 - d; d--; }
    const int kt = pp, it = pp + d;
    const int i0 = it * 128, k0 = kt * 128;

    int jbeg = k0, jend = (it + 1) * 128;
    const int mid = jbeg + ((jend - jbeg) >> 1);
    if (seg == 0) jend = mid; else jbeg = mid;
    const int nch = (jend - jbeg) >> 6;

    const int tid = threadIdx.x;
    const int wid = tid >> 5, lane = tid & 31;

    const int ltile = tid >> 6;
    const int llane = tid & 63;
    const int rl = llane >> 3;
    const int c16 = llane & 7;
    const size_t boff = (size_t)b * SS * SS;
    const __nv_bfloat16* src =
        (ltile == 0) ? g_t1h + boff + (size_t)i0 * SS :
        (ltile == 1) ? g_t1l + boff + (size_t)i0 * SS :
        (ltile == 2) ? g_sgh + boff + (size_t)k0 * SS :
                       g_sgl + boff + (size_t)k0 * SS;
    const __nv_bfloat16* gbase = src + (size_t)rl * SS + c16 * 8;
    const uint32_t tsm = tiles + ltile * 16384;

#define SU_LOAD_CHUNK(stage, j0v) do { \
    const __nv_bfloat16* _g = gbase + (j0v); \
    const uint32_t _base = tsm + (stage) * 65536; \
    _Pragma("unroll") \
    for (int q = 0; q < 16; q++) { \
        uint32_t so = (uint32_t)((q * 8 + rl) * 128 + c16 * 16); \
        uint32_t sa = _base + SW128(so); \
        asm volatile("cp.async.cg.shared.global [%0], [%1], 16;" :: "r"(sa), "l"(_g + (size_t)q * 8 * SS)); \
    } \
    asm volatile("cp.async.commit_group;"); \
} while (0)

    float acc[2][8][4];
#pragma unroll
    for (int mf = 0; mf < 2; mf++)
#pragma unroll
        for (int nf = 0; nf < 8; nf++)
#pragma unroll
            for (int q = 0; q < 4; q++) acc[mf][nf][q] = 0.f;

    const int wm = wid >> 1, wn = wid & 1;
    const int lrow = lane & 15;
    const uint32_t kbl = (lane >> 4) * 16;

    SU_LOAD_CHUNK(0, jbeg);

    for (int i = 0; i < nch; i++) {
        const int s = i & 1;
        if (i + 1 < nch) {
            SU_LOAD_CHUNK(s ^ 1, jbeg + (i + 1) * 64);
            asm volatile("cp.async.wait_group 1;");
        } else {
            asm volatile("cp.async.wait_group 0;");
        }
        __syncthreads();

        const uint32_t stAh = tiles + s * 65536;
        const uint32_t stAl = stAh + 16384;
        const uint32_t stBh = stAh + 32768;
        const uint32_t stBl = stAh + 49152;

#pragma unroll
        for (int ks = 0; ks < 4; ks++) {
            const uint32_t kb = ks * 32 + kbl;
            uint32_t ah[2][4], al[2][4], bh[4][4], bl[4][4];
#pragma unroll
            for (int mf = 0; mf < 2; mf++) {
                const uint32_t off = SW128((uint32_t)((wm * 32 + mf * 16 + lrow) * 128) + kb);
                ldsm4(ah[mf], stAh + off);
                ldsm4(al[mf], stAl + off);
            }
#pragma unroll
            for (int np = 0; np < 4; np++) {
                const uint32_t off = SW128((uint32_t)((wn * 64 + np * 16 + lrow) * 128) + kb);
                ldsm4(bh[np], stBh + off);
                ldsm4(bl[np], stBl + off);
            }
#pragma unroll
            for (int mf = 0; mf < 2; mf++)
#pragma unroll
                for (int nf = 0; nf < 8; nf++) {
                    const int np = nf >> 1, sel = nf & 1;
                    mma16816(acc[mf][nf], ah[mf], bh[np][sel], bh[np][sel + 2]);
                    mma16816(acc[mf][nf], ah[mf], bl[np][sel], bl[np][sel + 2]);
                    mma16816(acc[mf][nf], al[mf], bh[np][sel], bh[np][sel + 2]);
                }
        }
        __syncthreads();
    }
#undef SU_LOAD_CHUNK

    float* C = (seg ? g_suB : g_suA) + boff;
    const int rr = lane >> 2, cc = (lane & 3) * 2;
#pragma unroll
    for (int mf = 0; mf < 2; mf++) {
        const int gr = i0 + wm * 32 + mf * 16 + rr;
#pragma unroll
        for (int nf = 0; nf < 8; nf++) {
            const int gc = k0 + wn * 64 + nf * 8 + cc;
            *(float2*)(C + (size_t)gr * SS + gc) = make_float2(acc[mf][nf][0], acc[mf][nf][1]);
            *(float2*)(C + (size_t)(gr + 8) * SS + gc) = make_float2(acc[mf][nf][2], acc[mf][nf][3]);
        }
    }
}

// ---------------------------------------------------------------------------
// K4: split-KV flash attention partial (unchanged)
// ---------------------------------------------------------------------------
__global__ void __launch_bounds__(256) k_attn_part() {
    const int it = blockIdx.x, chunk = blockIdx.y, b = blockIdx.z;
    if (chunk * 8 > it) return;
    const int kt_beg = chunk * 8;
    const int kt_end = min(kt_beg + 8, it + 1);
    const int i0 = it * 64;

    extern __shared__ float sm[];
    float* Qs  = sm;
    float* KVs = sm + 64 * 68;
    float* Ps  = sm + 2 * 64 * 68;

    const float* Qc  = g_P[3] + (size_t)b * SS * DHE;
    const float* Kc  = g_P[4] + (size_t)b * SS * DHE;
    const float* Vc  = g_P[5] + (size_t)b * SS * DHE;
    const float* SuA = g_suA + (size_t)b * SS * SS;
    const float* SuB = g_suB + (size_t)b * SS * SS;

    const int tid = threadIdx.x;
    const int tx = tid & 15, ty = tid >> 4;

    for (int t = tid; t < 64 * 16; t += 256) {
        int r = t >> 4, c4 = (t & 15) * 4;
        float4 v = *(const float4*)(Qc + (size_t)(i0 + r) * DHE + c4);
        Qs[(c4 + 0) * 68 + r] = v.x; Qs[(c4 + 1) * 68 + r] = v.y;
        Qs[(c4 + 2) * 68 + r] = v.z; Qs[(c4 + 3) * 68 + r] = v.w;
    }

    float m[4], l[4], O[4][4];
#pragma unroll
    for (int r = 0; r < 4; r++) {
        m[r] = -1e30f; l[r] = 0.f;
#pragma unroll
        for (int c = 0; c < 4; c++) O[r][c] = 0.f;
    }

    for (int kt = kt_beg; kt < kt_end; kt++) {
        const int k0 = kt * 64;
        __syncthreads();
        for (int t = tid; t < 64 * 16; t += 256) {
            int r = t >> 4, c4 = (t & 15) * 4;
            float4 v = *(const float4*)(Kc + (size_t)(k0 + r) * DHE + c4);
            KVs[(c4 + 0) * 68 + r] = v.x; KVs[(c4 + 1) * 68 + r] = v.y;
            KVs[(c4 + 2) * 68 + r] = v.z; KVs[(c4 + 3) * 68 + r] = v.w;
        }
        __syncthreads();

        float s[4][4];
#pragma unroll
        for (int i = 0; i < 4; i++)
#pragma unroll
            for (int j = 0; j < 4; j++) s[i][j] = 0.f;
#pragma unroll
        for (int d = 0; d < 64; d++) {
            float qr[4], kr[4];
            *(float4*)qr = *(float4*)&Qs[d * 68 + ty * 4];
            *(float4*)kr = *(float4*)&KVs[d * 68 + tx * 4];
#pragma unroll
            for (int i = 0; i < 4; i++)
#pragma unroll
                for (int j = 0; j < 4; j++) s[i][j] = fmaf(qr[i], kr[j], s[i][j]);
        }

        float lg[4][4];
#pragma unroll
        for (int r = 0; r < 4; r++) {
            const int gi = i0 + ty * 4 + r;
            float4 a4 = *(const float4*)(SuA + (size_t)gi * SS + k0 + tx * 4);
            float4 b4 = *(const float4*)(SuB + (size_t)gi * SS + k0 + tx * 4);
            float su[4] = {a4.x + b4.x, a4.y + b4.y, a4.z + b4.z, a4.w + b4.w};
#pragma unroll
            for (int c = 0; c < 4; c++) {
                const int gk = k0 + tx * 4 + c;
                float v = s[r][c] * SCALE - fast_silu(su[c]);
                if (gk > gi) v = -1e30f;
                lg[r][c] = v;
            }
        }

#pragma unroll
        for (int r = 0; r < 4; r++) {
            float mx = fmaxf(fmaxf(lg[r][0], lg[r][1]), fmaxf(lg[r][2], lg[r][3]));
#pragma unroll
            for (int off = 1; off < 16; off <<= 1)
                mx = fmaxf(mx, __shfl_xor_sync(0xffffffffu, mx, off));
            const float mnew = fmaxf(m[r], mx);
            const float corr = __expf(m[r] - mnew);
            m[r] = mnew;
            float ps = 0.f;
#pragma unroll
            for (int c = 0; c < 4; c++) {
                const float p = __expf(lg[r][c] - mnew);
                lg[r][c] = p;
                ps += p;
            }
#pragma unroll
            for (int off = 1; off < 16; off <<= 1)
                ps += __shfl_xor_sync(0xffffffffu, ps, off);
            l[r] = l[r] * corr + ps;
#pragma unroll
            for (int c = 0; c < 4; c++) O[r][c] *= corr;
        }

#pragma unroll
        for (int r = 0; r < 4; r++)
#pragma unroll
            for (int c = 0; c < 4; c++)
                Ps[(tx * 4 + c) * 68 + (ty * 4 + r)] = lg[r][c];

        __syncthreads();

        for (int t = tid; t < 64 * 16; t += 256) {
            int r = t >> 4, c4 = (t & 15) * 4;
            *(float4*)&KVs[r * 68 + c4] = *(const float4*)(Vc + (size_t)(k0 + r) * DHE + c4);
        }
        __syncthreads();

#pragma unroll
        for (int kk = 0; kk < 64; kk++) {
            float pr[4], vr[4];
            *(float4*)pr = *(float4*)&Ps[kk * 68 + ty * 4];
            *(float4*)vr = *(float4*)&KVs[kk * 68 + tx * 4];
#pragma unroll
            for (int i = 0; i < 4; i++)
#pragma unroll
                for (int j = 0; j < 4; j++) O[i][j] = fmaf(pr[i], vr[j], O[i][j]);
        }
    }

#pragma unroll
    for (int r = 0; r < 4; r++) {
        const int lr = ty * 4 + r;
        if (tx == 0) {
            g_am[b][chunk][it][lr] = m[r];
            g_al[b][chunk][it][lr] = l[r];
        }
        *(float4*)&g_aO[b][chunk][it][lr * 64 + tx * 4] =
            make_float4(O[r][0], O[r][1], O[r][2], O[r][3]);
    }
}

// ---------------------------------------------------------------------------
// K5: combine split-KV partials (unchanged)
// ---------------------------------------------------------------------------
__global__ void k_comb(float* __restrict__ out) {
    const int it = blockIdx.x, b = blockIdx.y;
    const int nch = it / 8 + 1;
    const int tid = threadIdx.x;
    const int r = tid >> 2;
    const int c0 = (tid & 3) * 16;

    float M = -1e30f;
#pragma unroll
    for (int c = 0; c < 4; c++)
        if (c < nch) M = fmaxf(M, g_am[b][c][it][r]);

    float w[4] = {0.f, 0.f, 0.f, 0.f};
    float lt = 0.f;
#pragma unroll
    for (int c = 0; c < 4; c++)
        if (c < nch) {
            const float wv = __expf(g_am[b][c][it][r] - M);
            w[c] = wv;
            lt += g_al[b][c][it][r] * wv;
        }
    const float inv = 1.f / lt;

    float* dst = out + ((size_t)b * SS + it * 64 + r) * DHE + c0;
#pragma unroll
    for (int j4 = 0; j4 < 4; j4++) {
        float4 acc = make_float4(0.f, 0.f, 0.f, 0.f);
#pragma unroll
        for (int c = 0; c < 4; c++)
            if (c < nch) {
                float4 v = *(const float4*)&g_aO[b][c][it][r * 64 + c0 + j4 * 4];
                acc.x = fmaf(v.x, w[c], acc.x);
                acc.y = fmaf(v.y, w[c], acc.y);
                acc.z = fmaf(v.z, w[c], acc.z);
                acc.w = fmaf(v.w, w[c], acc.w);
            }
        *(float4*)(dst + j4 * 4) =
            make_float4(acc.x * inv, acc.y * inv, acc.z * inv, acc.w * inv);
    }
}

// ---------------------------------------------------------------------------
extern "C" void kernel_launch(void* const* d_in, const int* in_sizes, int n_in,
                              void* d_out, int out_size) {
    const float* x   = (const float*)d_in[0];
    const float* wqu = (const float*)d_in[1];
    const float* wku = (const float*)d_in[2];
    const float* wvu = (const float*)d_in[3];
    const float* wqc = (const float*)d_in[4];
    const float* wkc = (const float*)d_in[5];
    const float* wvc = (const float*)d_in[6];
    float* out = (float*)d_out;

    k_cvt_x<<<2048, 256>>>(x);
    k_cvt_w<<<192, 256>>>(wqu, wku, wvu, wqc, wkc, wvc);

    const int proj_smem = 1024 + 2 * 49152;  // 99328 B
    cudaFuncSetAttribute(k_proj_mma, cudaFuncAttributeMaxDynamicSharedMemorySize, proj_smem);
    k_proj_mma<<<dim3(64, 6), 256, proj_smem>>>();

    const int pair_smem = 1024 + 65536;  // 66560 B
    cudaFuncSetAttribute(k_pair_mma, cudaFuncAttributeMaxDynamicSharedMemorySize, pair_smem);
    k_pair_mma<<<dim3(136, 4, 2), 256, pair_smem>>>();

    const int su_smem = 1024 + 2 * 65536;  // 132096 B
    cudaFuncSetAttribute(k_su_mma, cudaFuncAttributeMaxDynamicSharedMemorySize, su_smem);
    k_su_mma<<<dim3(272, 1, 4), 256, su_smem>>>();

    const int attn_smem = 3 * 64 * 68 * 4;  // 52224 B
    cudaFuncSetAttribute(k_attn_part, cudaFuncAttributeMaxDynamicSharedMemorySize, attn_smem);
    k_attn_part<<<dim3(32, 4, 4), 256, attn_smem>>>();
    k_comb<<<dim3(32, 4), 256>>>(out);
}

// round 8
// speedup vs baseline: 3.3967x; 1.2040x over previous
#include <cuda_runtime.h>
#include <cuda_bf16.h>
#include <cstdint>

#define BB 4
#define SS 2048
#define DD 1024
#define DHE 64
#define SCALE 0.125f

// ---------------- scratch (device globals) ----------------
static __device__ float g_P[6][BB * SS * DHE];  // 0=Qu 1=Ku 2=Vu 3=Qc 4=Kc 5=Vc
static __device__ __nv_bfloat16 g_Ph[5][BB * SS * DHE];  // hi of Qu,Ku,Vu,Qc,Kc
static __device__ __nv_bfloat16 g_Pl[5][BB * SS * DHE];  // lo
static __device__ __nv_bfloat16 g_Vth[(size_t)BB * DHE * SS];  // Vc transposed [b][d][s]
static __device__ __nv_bfloat16 g_Vtl[(size_t)BB * DHE * SS];
static __device__ __nv_bfloat16 g_xh[(size_t)BB * SS * DD];
static __device__ __nv_bfloat16 g_xl[(size_t)BB * SS * DD];
static __device__ __nv_bfloat16 g_wh[6][DHE * DD];  // transposed: [head][n][k]
static __device__ __nv_bfloat16 g_wl[6][DHE * DD];
static __device__ __nv_bfloat16 g_t1h[(size_t)BB * SS * SS];
static __device__ __nv_bfloat16 g_t1l[(size_t)BB * SS * SS];
static __device__ __nv_bfloat16 g_sgh[(size_t)BB * SS * SS];
static __device__ __nv_bfloat16 g_sgl[(size_t)BB * SS * SS];
static __device__ float g_suA[(size_t)BB * SS * SS];
static __device__ float g_suB[(size_t)BB * SS * SS];
// split-KV partials: 8 chunks (2 k-tiles of 128 each), 16 i-tiles of 128 rows
static __device__ float g_am[BB][8][16][128];
static __device__ float g_al[BB][8][16][128];
static __device__ float g_aO[BB][8][16][128 * 64];

// ---------------- helpers (compute_103-safe: no 'a' features) ----------------
__device__ __forceinline__ uint32_t smem_to_u32(const void* p) {
    uint32_t a;
    asm("{ .reg .u64 t; cvta.to.shared.u64 t, %1; cvt.u32.u64 %0, t; }" : "=r"(a) : "l"(p));
    return a;
}
#define SW128(o) ((o) ^ (((o) >> 3) & 0x70))

__device__ __forceinline__ void ldsm4(uint32_t* r, uint32_t addr) {
    asm volatile("ldmatrix.sync.aligned.m8n8.x4.shared.b16 {%0,%1,%2,%3}, [%4];"
        : "=r"(r[0]), "=r"(r[1]), "=r"(r[2]), "=r"(r[3]) : "r"(addr));
}
__device__ __forceinline__ void mma16816(float* c, const uint32_t* a,
                                         uint32_t b0, uint32_t b1) {
    asm volatile("mma.sync.aligned.m16n8k16.row.col.f32.bf16.bf16.f32 "
        "{%0,%1,%2,%3}, {%4,%5,%6,%7}, {%8,%9}, {%0,%1,%2,%3};"
        : "+f"(c[0]), "+f"(c[1]), "+f"(c[2]), "+f"(c[3])
        : "r"(a[0]), "r"(a[1]), "r"(a[2]), "r"(a[3]), "r"(b0), "r"(b1));
}

__device__ __forceinline__ float fast_rcp(float y) {
    float r = __int_as_float(0x7EF127EAu - __float_as_int(y));
    r = r * fmaf(-y, r, 2.0f);
    r = r * fmaf(-y, r, 2.0f);
    r = r * fmaf(-y, r, 2.0f);
    return r;
}
__device__ __forceinline__ float fast_sigmoid(float x) {
    const float t = __expf(-fmaxf(x, -80.f));
    return fast_rcp(1.f + t);
}
__device__ __forceinline__ float fast_silu(float x) {
    return x * fast_sigmoid(x);
}
__device__ __forceinline__ void split2(float v0, float v1, uint32_t& h, uint32_t& l) {
    const __nv_bfloat16 h0 = __float2bfloat16(v0), h1 = __float2bfloat16(v1);
    const __nv_bfloat16 l0 = __float2bfloat16(v0 - __bfloat162float(h0));
    const __nv_bfloat16 l1 = __float2bfloat16(v1 - __bfloat162float(h1));
    union { __nv_bfloat162 b; uint32_t u; } H, L;
    H.b = __halves2bfloat162(h0, h1);
    L.b = __halves2bfloat162(l0, l1);
    h = H.u; l = L.u;
}

// ---------------------------------------------------------------------------
// K0a: convert x -> bf16 hi/lo
// ---------------------------------------------------------------------------
__global__ void k_cvt_x(const float* __restrict__ x) {
    const size_t n = (size_t)BB * SS * DD;
    for (size_t i = (size_t)blockIdx.x * blockDim.x + threadIdx.x; i < n;
         i += (size_t)gridDim.x * blockDim.x) {
        const float v = x[i];
        const __nv_bfloat16 h = __float2bfloat16(v);
        g_xh[i] = h;
        g_xl[i] = __float2bfloat16(v - __bfloat162float(h));
    }
}
// K0b: convert+transpose weights -> [head][n][k] bf16 hi/lo
__global__ void k_cvt_w(const float* __restrict__ w0, const float* __restrict__ w1,
                        const float* __restrict__ w2, const float* __restrict__ w3,
                        const float* __restrict__ w4, const float* __restrict__ w5) {
    const int n = 6 * DD * DHE;
    for (int i = blockIdx.x * blockDim.x + threadIdx.x; i < n;
         i += gridDim.x * blockDim.x) {
        const int head = i >> 16;
        const int rem = i & 65535;
        const int k = rem >> 6, nn = rem & 63;
        const float* w = head == 0 ? w0 : head == 1 ? w1 : head == 2 ? w2
                       : head == 3 ? w3 : head == 4 ? w4 : w5;
        const float v = w[k * DHE + nn];
        const __nv_bfloat16 h = __float2bfloat16(v);
        g_wh[head][nn * DD + k] = h;
        g_wl[head][nn * DD + k] = __float2bfloat16(v - __bfloat162float(h));
    }
}

// ---------------------------------------------------------------------------
// K1: projections via mma.sync bf16 hi/lo.  out[h] = x @ w[h].
// Emits bf16 hi/lo row-major copies for heads 0..4.
// ---------------------------------------------------------------------------
__global__ void __launch_bounds__(256) k_proj_mma() {
    extern __shared__ char smem[];
    const uint32_t tiles = (smem_to_u32(smem) + 1023u) & ~1023u;
    const int row0 = blockIdx.x * 128, head = blockIdx.y;

    const int tid = threadIdx.x;
    const int wid = tid >> 5, lane = tid & 31;
    const int wm = wid & 3, wn = wid >> 2;
    const int lrow = lane & 15;
    const uint32_t kbl = (lane >> 4) * 16;

#define PJ_LOAD(stage, ch) do { \
    const uint32_t _st = tiles + (stage) * 49152; \
    _Pragma("unroll") \
    for (int q = 0; q < 4; q++) { \
        const int r = (tid >> 3) + q * 32; \
        const int c16 = tid & 7; \
        const uint32_t so = SW128((uint32_t)(r * 128 + c16 * 16)); \
        const size_t go = (size_t)(row0 + r) * DD + (ch) + c16 * 8; \
        asm volatile("cp.async.cg.shared.global [%0], [%1], 16;" :: "r"(_st + so), "l"(g_xh + go)); \
        asm volatile("cp.async.cg.shared.global [%0], [%1], 16;" :: "r"(_st + 16384 + so), "l"(g_xl + go)); \
    } \
    _Pragma("unroll") \
    for (int q = 0; q < 2; q++) { \
        const int r = (tid >> 3) + q * 32; \
        const int c16 = tid & 7; \
        const uint32_t so = SW128((uint32_t)(r * 128 + c16 * 16)); \
        const size_t go = (size_t)r * DD + (ch) + c16 * 8; \
        asm volatile("cp.async.cg.shared.global [%0], [%1], 16;" :: "r"(_st + 32768 + so), "l"(g_wh[head] + go)); \
        asm volatile("cp.async.cg.shared.global [%0], [%1], 16;" :: "r"(_st + 40960 + so), "l"(g_wl[head] + go)); \
    } \
    asm volatile("cp.async.commit_group;"); \
} while (0)

    float acc[2][4][4];
#pragma unroll
    for (int mf = 0; mf < 2; mf++)
#pragma unroll
        for (int nf = 0; nf < 4; nf++)
#pragma unroll
            for (int q = 0; q < 4; q++) acc[mf][nf][q] = 0.f;

    PJ_LOAD(0, 0);

    for (int c = 0; c < DD / 64; c++) {
        const int s = c & 1;
        if (c + 1 < DD / 64) {
            PJ_LOAD(s ^ 1, (c + 1) * 64);
            asm volatile("cp.async.wait_group 1;");
        } else {
            asm volatile("cp.async.wait_group 0;");
        }
        __syncthreads();

        const uint32_t stAh = tiles + s * 49152;
        const uint32_t stAl = stAh + 16384;
        const uint32_t stBh = stAh + 32768;
        const uint32_t stBl = stAh + 40960;

#pragma unroll
        for (int ks = 0; ks < 4; ks++) {
            const uint32_t kb = ks * 32 + kbl;
            uint32_t ah[2][4], al[2][4], bh[2][4], bl[2][4];
#pragma unroll
            for (int mf = 0; mf < 2; mf++) {
                const uint32_t off = SW128((uint32_t)((wm * 32 + mf * 16 + lrow) * 128) + kb);
                ldsm4(ah[mf], stAh + off);
                ldsm4(al[mf], stAl + off);
            }
#pragma unroll
            for (int np = 0; np < 2; np++) {
                const uint32_t off = SW128((uint32_t)((wn * 32 + np * 16 + lrow) * 128) + kb);
                ldsm4(bh[np], stBh + off);
                ldsm4(bl[np], stBl + off);
            }
#pragma unroll
            for (int mf = 0; mf < 2; mf++)
#pragma unroll
                for (int nf = 0; nf < 4; nf++) {
                    const int np = nf >> 1, sel = nf & 1;
                    mma16816(acc[mf][nf], ah[mf], bh[np][sel], bh[np][sel + 2]);
                    mma16816(acc[mf][nf], ah[mf], bl[np][sel], bl[np][sel + 2]);
                    mma16816(acc[mf][nf], al[mf], bh[np][sel], bh[np][sel + 2]);
                }
        }
        __syncthreads();
    }
#undef PJ_LOAD

    float* C = g_P[head];
    const int rr = lane >> 2, cc = (lane & 3) * 2;
#pragma unroll
    for (int mf = 0; mf < 2; mf++) {
        const int gr = row0 + wm * 32 + mf * 16 + rr;
#pragma unroll
        for (int nf = 0; nf < 4; nf++) {
            const int gc = wn * 32 + nf * 8 + cc;
            *(float2*)(C + (size_t)gr * DHE + gc) = make_float2(acc[mf][nf][0], acc[mf][nf][1]);
            *(float2*)(C + (size_t)(gr + 8) * DHE + gc) = make_float2(acc[mf][nf][2], acc[mf][nf][3]);
        }
    }
    if (head < 5) {
        __nv_bfloat16* Hh = g_Ph[head];
        __nv_bfloat16* Hl = g_Pl[head];
#pragma unroll
        for (int mf = 0; mf < 2; mf++) {
            const int gr = row0 + wm * 32 + mf * 16 + rr;
#pragma unroll
            for (int nf = 0; nf < 4; nf++) {
                const int gc = wn * 32 + nf * 8 + cc;
                uint32_t h0, l0, h1, l1;
                split2(acc[mf][nf][0], acc[mf][nf][1], h0, l0);
                split2(acc[mf][nf][2], acc[mf][nf][3], h1, l1);
                *(uint32_t*)(Hh + (size_t)gr * DHE + gc) = h0;
                *(uint32_t*)(Hl + (size_t)gr * DHE + gc) = l0;
                *(uint32_t*)(Hh + (size_t)(gr + 8) * DHE + gc) = h1;
                *(uint32_t*)(Hl + (size_t)(gr + 8) * DHE + gc) = l1;
            }
        }
    }
}

// ---------------------------------------------------------------------------
// K1b: transpose Vc -> [b][d][s] bf16 hi/lo.  grid (32 s-tiles, 4 b), 256 thr.
// ---------------------------------------------------------------------------
__global__ void k_vt() {
    __shared__ float ts[64][65];
    const int s0 = blockIdx.x * 64, b = blockIdx.y;
    const int tid = threadIdx.x;
    for (int t = tid; t < 4096; t += 256) {
        const int r = t >> 6, c = t & 63;
        ts[r][c] = g_P[5][((size_t)b * SS + s0 + r) * DHE + c];
    }
    __syncthreads();
    for (int t = tid; t < 4096; t += 256) {
        const int d = t >> 6, sc = t & 63;
        const float v = ts[sc][d];
        const __nv_bfloat16 h = __float2bfloat16(v);
        const size_t o = ((size_t)b * DHE + d) * SS + s0 + sc;
        g_Vth[o] = h;
        g_Vtl[o] = __float2bfloat16(v - __bfloat162float(h));
    }
}

// ---------------------------------------------------------------------------
// K2: term1 / sigmoid gate via mma.sync, 128x128 tiles (unchanged)
// ---------------------------------------------------------------------------
__global__ void __launch_bounds__(256) k_pair_mma() {
    extern __shared__ char smem[];
    const uint32_t tiles = (smem_to_u32(smem) + 1023u) & ~1023u;

    const int mode = blockIdx.z, b = blockIdx.y;
    int pp = blockIdx.x;
    int d = 15;
    while (pp >= 16 - d) { pp -= 16 - d; d--; }
    const int rt = (mode == 0) ? (pp + d) : pp;
    const int ct = (mode == 0) ? pp : (pp + d);
    const int i0 = rt * 128, j0 = ct * 128;
    const int hA = (mode == 0) ? 3 : 0;
    const int hB = (mode == 0) ? 2 : 1;

    const int tid = threadIdx.x;
    const int wid = tid >> 5, lane = tid & 31;

    {
        const int ltile = tid >> 6;
        const int llane = tid & 63;
        const int rl = llane >> 3, c16 = llane & 7;
        const __nv_bfloat16* src =
            (ltile == 0) ? g_Ph[hA] + ((size_t)b * SS + i0) * DHE :
            (ltile == 1) ? g_Pl[hA] + ((size_t)b * SS + i0) * DHE :
            (ltile == 2) ? g_Ph[hB] + ((size_t)b * SS + j0) * DHE :
                           g_Pl[hB] + ((size_t)b * SS + j0) * DHE;
        const __nv_bfloat16* g = src + (size_t)rl * DHE + c16 * 8;
        const uint32_t tsm = tiles + ltile * 16384;
#pragma unroll
        for (int q = 0; q < 16; q++) {
            const uint32_t so = SW128((uint32_t)((q * 8 + rl) * 128 + c16 * 16));
            asm volatile("cp.async.cg.shared.global [%0], [%1], 16;"
                :: "r"(tsm + so), "l"(g + (size_t)q * 8 * DHE));
        }
        asm volatile("cp.async.commit_group;");
        asm volatile("cp.async.wait_group 0;");
    }
    __syncthreads();

    float acc[2][8][4];
#pragma unroll
    for (int mf = 0; mf < 2; mf++)
#pragma unroll
        for (int nf = 0; nf < 8; nf++)
#pragma unroll
            for (int q = 0; q < 4; q++) acc[mf][nf][q] = 0.f;

    const int wm = wid >> 1, wn = wid & 1;
    const int lrow = lane & 15;
    const uint32_t kbl = (lane >> 4) * 16;
    const uint32_t stAh = tiles, stAl = tiles + 16384;
    const uint32_t stBh = tiles + 32768, stBl = tiles + 49152;

#pragma unroll
    for (int ks = 0; ks < 4; ks++) {
        const uint32_t kb = ks * 32 + kbl;
        uint32_t ah[2][4], al[2][4], bh[4][4], bl[4][4];
#pragma unroll
        for (int mf = 0; mf < 2; mf++) {
            const uint32_t off = SW128((uint32_t)((wm * 32 + mf * 16 + lrow) * 128) + kb);
            ldsm4(ah[mf], stAh + off);
            ldsm4(al[mf], stAl + off);
        }
#pragma unroll
        for (int np = 0; np < 4; np++) {
            const uint32_t off = SW128((uint32_t)((wn * 64 + np * 16 + lrow) * 128) + kb);
            ldsm4(bh[np], stBh + off);
            ldsm4(bl[np], stBl + off);
        }
#pragma unroll
        for (int mf = 0; mf < 2; mf++)
#pragma unroll
            for (int nf = 0; nf < 8; nf++) {
                const int np = nf >> 1, sel = nf & 1;
                mma16816(acc[mf][nf], ah[mf], bh[np][sel], bh[np][sel + 2]);
                mma16816(acc[mf][nf], ah[mf], bl[np][sel], bl[np][sel + 2]);
                mma16816(acc[mf][nf], al[mf], bh[np][sel], bh[np][sel + 2]);
            }
    }

    const size_t boff = (size_t)b * SS * SS;
    __nv_bfloat16* outh = (mode == 0 ? g_t1h : g_sgh) + boff;
    __nv_bfloat16* outl = (mode == 0 ? g_t1l : g_sgl) + boff;
    const int rr = lane >> 2, cc = (lane & 3) * 2;
#pragma unroll
    for (int mf = 0; mf < 2; mf++) {
#pragma unroll
        for (int half = 0; half < 2; half++) {
            const int gi = i0 + wm * 32 + mf * 16 + half * 8 + rr;
#pragma unroll
            for (int nf = 0; nf < 8; nf++) {
                const int gc = j0 + wn * 64 + nf * 8 + cc;
                float v0 = acc[mf][nf][half * 2 + 0] * SCALE;
                float v1 = acc[mf][nf][half * 2 + 1] * SCALE;
                if (mode == 0) {
                    v0 = (gc <= gi) ? v0 : 0.f;
                    v1 = (gc + 1 <= gi) ? v1 : 0.f;
                } else {
                    v0 = (gc > gi) ? fast_sigmoid(v0) : 0.f;
                    v1 = (gc + 1 > gi) ? fast_sigmoid(v1) : 0.f;
                }
                uint32_t h, l;
                split2(v0, v1, h, l);
                *(uint32_t*)(outh + (size_t)gi * SS + gc) = h;
                *(uint32_t*)(outl + (size_t)gi * SS + gc) = l;
            }
        }
    }
}

// ---------------------------------------------------------------------------
// K3: S_u via mma.sync bf16x2-split (unchanged)
// ---------------------------------------------------------------------------
__global__ void __launch_bounds__(256) k_su_mma() {
    extern __shared__ char smem[];
    const uint32_t tiles = (smem_to_u32(smem) + 1023u) & ~1023u;

    const int b = blockIdx.z;
    const int seg = blockIdx.x & 1;
    int pp = blockIdx.x >> 1;
    int d = 15;
    while (pp >= 16 - d) { pp -= 16 - d; d--; }
    const int kt = pp, it = pp + d;
    const int i0 = it * 128, k0 = kt * 128;

    int jbeg = k0, jend = (it + 1) * 128;
    const int mid = jbeg + ((jend - jbeg) >> 1);
    if (seg == 0) jend = mid; else jbeg = mid;
    const int nch = (jend - jbeg) >> 6;

    const int tid = threadIdx.x;
    const int wid = tid >> 5, lane = tid & 31;

    const int ltile = tid >> 6;
    const int llane = tid & 63;
    const int rl = llane >> 3;
    const int c16 = llane & 7;
    const size_t boff = (size_t)b * SS * SS;
    const __nv_bfloat16* src =
        (ltile == 0) ? g_t1h + boff + (size_t)i0 * SS :
        (ltile == 1) ? g_t1l + boff + (size_t)i0 * SS :
        (ltile == 2) ? g_sgh + boff + (size_t)k0 * SS :
                       g_sgl + boff + (size_t)k0 * SS;
    const __nv_bfloat16* gbase = src + (size_t)rl * SS + c16 * 8;
    const uint32_t tsm = tiles + ltile * 16384;

#define SU_LOAD_CHUNK(stage, j0v) do { \
    const __nv_bfloat16* _g = gbase + (j0v); \
    const uint32_t _base = tsm + (stage) * 65536; \
    _Pragma("unroll") \
    for (int q = 0; q < 16; q++) { \
        uint32_t so = (uint32_t)((q * 8 + rl) * 128 + c16 * 16); \
        uint32_t sa = _base + SW128(so); \
        asm volatile("cp.async.cg.shared.global [%0], [%1], 16;" :: "r"(sa), "l"(_g + (size_t)q * 8 * SS)); \
    } \
    asm volatile("cp.async.commit_group;"); \
} while (0)

    float acc[2][8][4];
#pragma unroll
    for (int mf = 0; mf < 2; mf++)
#pragma unroll
        for (int nf = 0; nf < 8; nf++)
#pragma unroll
            for (int q = 0; q < 4; q++) acc[mf][nf][q] = 0.f;

    const int wm = wid >> 1, wn = wid & 1;
    const int lrow = lane & 15;
    const uint32_t kbl = (lane >> 4) * 16;

    SU_LOAD_CHUNK(0, jbeg);

    for (int i = 0; i < nch; i++) {
        const int s = i & 1;
        if (i + 1 < nch) {
            SU_LOAD_CHUNK(s ^ 1, jbeg + (i + 1) * 64);
            asm volatile("cp.async.wait_group 1;");
        } else {
            asm volatile("cp.async.wait_group 0;");
        }
        __syncthreads();

        const uint32_t stAh = tiles + s * 65536;
        const uint32_t stAl = stAh + 16384;
        const uint32_t stBh = stAh + 32768;
        const uint32_t stBl = stAh + 49152;

#pragma unroll
        for (int ks = 0; ks < 4; ks++) {
            const uint32_t kb = ks * 32 + kbl;
            uint32_t ah[2][4], al[2][4], bh[4][4], bl[4][4];
#pragma unroll
            for (int mf = 0; mf < 2; mf++) {
                const uint32_t off = SW128((uint32_t)((wm * 32 + mf * 16 + lrow) * 128) + kb);
                ldsm4(ah[mf], stAh + off);
                ldsm4(al[mf], stAl + off);
            }
#pragma unroll
            for (int np = 0; np < 4; np++) {
                const uint32_t off = SW128((uint32_t)((wn * 64 + np * 16 + lrow) * 128) + kb);
                ldsm4(bh[np], stBh + off);
                ldsm4(bl[np], stBl + off);
            }
#pragma unroll
            for (int mf = 0; mf < 2; mf++)
#pragma unroll
                for (int nf = 0; nf < 8; nf++) {
                    const int np = nf >> 1, sel = nf & 1;
                    mma16816(acc[mf][nf], ah[mf], bh[np][sel], bh[np][sel + 2]);
                    mma16816(acc[mf][nf], ah[mf], bl[np][sel], bl[np][sel + 2]);
                    mma16816(acc[mf][nf], al[mf], bh[np][sel], bh[np][sel + 2]);
                }
        }
        __syncthreads();
    }
#undef SU_LOAD_CHUNK

    float* C = (seg ? g_suB : g_suA) + boff;
    const int rr = lane >> 2, cc = (lane & 3) * 2;
#pragma unroll
    for (int mf = 0; mf < 2; mf++) {
        const int gr = i0 + wm * 32 + mf * 16 + rr;
#pragma unroll
        for (int nf = 0; nf < 8; nf++) {
            const int gc = k0 + wn * 64 + nf * 8 + cc;
            *(float2*)(C + (size_t)gr * SS + gc) = make_float2(acc[mf][nf][0], acc[mf][nf][1]);
            *(float2*)(C + (size_t)(gr + 8) * SS + gc) = make_float2(acc[mf][nf][2], acc[mf][nf][3]);
        }
    }
}

// ---------------------------------------------------------------------------
// K4: flash attention partial via mma.sync.
// Block: 128 i-rows (it), 2 k-tiles of 128 (chunk).  8 warps, each m=16 rows.
// Sc = Qc*Kc^T (hi/lo x3); logits = Sc*SCALE - silu(SuA+SuB); online softmax
// in register fragments; P@V via fragment repack (hi/lo x3), V pre-transposed.
// grid (16 it, 8 chunk, 4 b), 256 thr, 99328 B smem.
// ---------------------------------------------------------------------------
__global__ void __launch_bounds__(256) k_attn_mma() {
    const int it = blockIdx.x, chunk = blockIdx.y, b = blockIdx.z;
    if (chunk * 2 > it) return;
    const int kt_beg = chunk * 2;
    const int kt_end = min(kt_beg + 2, it + 1);
    const int i0 = it * 128;

    extern __shared__ char smem[];
    const uint32_t sb = (smem_to_u32(smem) + 1023u) & ~1023u;
    const uint32_t smQ = sb;            // Qh 16K | Ql 16K
    const uint32_t smK = sb + 32768;    // Kh 16K | Kl 16K
    const uint32_t smV = sb + 65536;    // Vh 16K (2 subtiles) | Vl 16K

    const int tid = threadIdx.x;
    const int wid = tid >> 5, lane = tid & 31;
    const int m0 = wid * 16;
    const int lrow = lane & 15;
    const uint32_t kbl = (lane >> 4) * 16;
    const int rr = lane >> 2, cc = (lane & 3) * 2;

    // load Q tile (once)
    for (int t = tid; t < 2048; t += 256) {
        const int half = t >> 10, r = (t >> 3) & 127, c16 = t & 7;
        const __nv_bfloat16* src = (half ? g_Pl[3] : g_Ph[3])
            + ((size_t)b * SS + i0 + r) * DHE + c16 * 8;
        const uint32_t dst = smQ + half * 16384 + SW128((uint32_t)(r * 128 + c16 * 16));
        asm volatile("cp.async.cg.shared.global [%0], [%1], 16;" :: "r"(dst), "l"(src));
    }
    asm volatile("cp.async.commit_group;");

    const float* SuA = g_suA + (size_t)b * SS * SS;
    const float* SuB = g_suB + (size_t)b * SS * SS;

    float m[2] = {-1e30f, -1e30f}, l[2] = {0.f, 0.f};
    float accO[8][4];
#pragma unroll
    for (int nf = 0; nf < 8; nf++)
#pragma unroll
        for (int q = 0; q < 4; q++) accO[nf][q] = 0.f;

    for (int kt = kt_beg; kt < kt_end; kt++) {
        const int k0t = kt * 128;
        __syncthreads();  // previous ldmatrix reads done before overwrite
        for (int t = tid; t < 2048; t += 256) {
            const int half = t >> 10, r = (t >> 3) & 127, c16 = t & 7;
            const __nv_bfloat16* src = (half ? g_Pl[4] : g_Ph[4])
                + ((size_t)b * SS + k0t + r) * DHE + c16 * 8;
            const uint32_t dst = smK + half * 16384 + SW128((uint32_t)(r * 128 + c16 * 16));
            asm volatile("cp.async.cg.shared.global [%0], [%1], 16;" :: "r"(dst), "l"(src));
        }
        for (int t = tid; t < 2048; t += 256) {
            const int half = t >> 10, rw = (t >> 3) & 127, c16 = t & 7;
            const int dd = rw & 63, sub = rw >> 6;
            const __nv_bfloat16* src = (half ? g_Vtl : g_Vth)
                + ((size_t)b * DHE + dd) * SS + k0t + sub * 64 + c16 * 8;
            const uint32_t dst = smV + half * 16384 + sub * 8192
                + SW128((uint32_t)(dd * 128 + c16 * 16));
            asm volatile("cp.async.cg.shared.global [%0], [%1], 16;" :: "r"(dst), "l"(src));
        }
        asm volatile("cp.async.commit_group;");
        asm volatile("cp.async.wait_group 0;");
        __syncthreads();

        // ---- Sc = Q K^T (m16 x n128 x k64, 3 products) ----
        float accS[16][4];
#pragma unroll
        for (int nf = 0; nf < 16; nf++)
#pragma unroll
            for (int q = 0; q < 4; q++) accS[nf][q] = 0.f;

#pragma unroll
        for (int ks = 0; ks < 4; ks++) {
            const uint32_t kb = ks * 32 + kbl;
            uint32_t ah[4], al[4];
            const uint32_t aoff = SW128((uint32_t)((m0 + lrow) * 128) + kb);
            ldsm4(ah, smQ + aoff);
            ldsm4(al, smQ + 16384 + aoff);
#pragma unroll
            for (int np = 0; np < 8; np++) {
                uint32_t bh[4], bl[4];
                const uint32_t boffs = SW128((uint32_t)((np * 16 + lrow) * 128) + kb);
                ldsm4(bh, smK + boffs);
                ldsm4(bl, smK + 16384 + boffs);
#pragma unroll
                for (int sel = 0; sel < 2; sel++) {
                    const int nf = np * 2 + sel;
                    mma16816(accS[nf], ah, bh[sel], bh[sel + 2]);
                    mma16816(accS[nf], ah, bl[sel], bl[sel + 2]);
                    mma16816(accS[nf], al, bh[sel], bh[sel + 2]);
                }
            }
        }

        // ---- logits: scale, - silu(Su), causal mask on diagonal tile ----
        const bool diag = (kt == it);
#pragma unroll
        for (int nf = 0; nf < 16; nf++) {
            const int gk = k0t + nf * 8 + cc;
#pragma unroll
            for (int half = 0; half < 2; half++) {
                const int gi = i0 + m0 + half * 8 + rr;
                const float2 a2 = *(const float2*)(SuA + (size_t)gi * SS + gk);
                const float2 b2 = *(const float2*)(SuB + (size_t)gi * SS + gk);
                float v0 = accS[nf][half * 2 + 0] * SCALE - fast_silu(a2.x + b2.x);
                float v1 = accS[nf][half * 2 + 1] * SCALE - fast_silu(a2.y + b2.y);
                if (diag) {
                    if (gk > gi) v0 = -1e30f;
                    if (gk + 1 > gi) v1 = -1e30f;
                }
                accS[nf][half * 2 + 0] = v0;
                accS[nf][half * 2 + 1] = v1;
            }
        }

        // ---- online softmax (row = half of m16; reduce over lanes l&3) ----
#pragma unroll
        for (int half = 0; half < 2; half++) {
            float mx = -1e30f;
#pragma unroll
            for (int nf = 0; nf < 16; nf++)
                mx = fmaxf(mx, fmaxf(accS[nf][half * 2], accS[nf][half * 2 + 1]));
            mx = fmaxf(mx, __shfl_xor_sync(0xffffffffu, mx, 1));
            mx = fmaxf(mx, __shfl_xor_sync(0xffffffffu, mx, 2));
            const float mnew = fmaxf(m[half], mx);
            const float corr = __expf(m[half] - mnew);
            m[half] = mnew;
            float ps = 0.f;
#pragma unroll
            for (int nf = 0; nf < 16; nf++) {
                const float p0 = __expf(accS[nf][half * 2] - mnew);
                const float p1 = __expf(accS[nf][half * 2 + 1] - mnew);
                accS[nf][half * 2] = p0;
                accS[nf][half * 2 + 1] = p1;
                ps += p0 + p1;
            }
            ps += __shfl_xor_sync(0xffffffffu, ps, 1);
            ps += __shfl_xor_sync(0xffffffffu, ps, 2);
            l[half] = l[half] * corr + ps;
#pragma unroll
            for (int nf = 0; nf < 8; nf++) {
                accO[nf][half * 2] *= corr;
                accO[nf][half * 2 + 1] *= corr;
            }
        }

        // ---- O += P @ V  (m16 x n64 x k128, 3 products) ----
#pragma unroll
        for (int ks2 = 0; ks2 < 8; ks2++) {
            uint32_t pah[4], pal[4];
            split2(accS[2 * ks2][0], accS[2 * ks2][1], pah[0], pal[0]);
            split2(accS[2 * ks2][2], accS[2 * ks2][3], pah[1], pal[1]);
            split2(accS[2 * ks2 + 1][0], accS[2 * ks2 + 1][1], pah[2], pal[2]);
            split2(accS[2 * ks2 + 1][2], accS[2 * ks2 + 1][3], pah[3], pal[3]);
            const uint32_t sub = (ks2 >> 2) * 8192;
            const uint32_t kb2 = (ks2 & 3) * 32 + kbl;
#pragma unroll
            for (int np = 0; np < 4; np++) {
                uint32_t vh[4], vl[4];
                const uint32_t voff = sub + SW128((uint32_t)((np * 16 + lrow) * 128) + kb2);
                ldsm4(vh, smV + voff);
                ldsm4(vl, smV + 16384 + voff);
#pragma unroll
                for (int sel = 0; sel < 2; sel++) {
                    const int nf2 = np * 2 + sel;
                    mma16816(accO[nf2], pah, vh[sel], vh[sel + 2]);
                    mma16816(accO[nf2], pah, vl[sel], vl[sel + 2]);
                    mma16816(accO[nf2], pal, vh[sel], vh[sel + 2]);
                }
            }
        }
    }

    // ---- write partials ----
    if ((lane & 3) == 0) {
        g_am[b][chunk][it][m0 + rr] = m[0];
        g_am[b][chunk][it][m0 + 8 + rr] = m[1];
        g_al[b][chunk][it][m0 + rr] = l[0];
        g_al[b][chunk][it][m0 + 8 + rr] = l[1];
    }
    float* aO = g_aO[b][chunk][it];
#pragma unroll
    for (int nf = 0; nf < 8; nf++) {
        const int gc = nf * 8 + cc;
        *(float2*)(aO + (m0 + rr) * 64 + gc) = make_float2(accO[nf][0], accO[nf][1]);
        *(float2*)(aO + (m0 + 8 + rr) * 64 + gc) = make_float2(accO[nf][2], accO[nf][3]);
    }
}

// ---------------------------------------------------------------------------
// K5: combine split-KV partials.  grid (16 it, 4 b), 256 thr.
// ---------------------------------------------------------------------------
__global__ void k_comb(float* __restrict__ out) {
    const int it = blockIdx.x, b = blockIdx.y;
    const int nch = it / 2 + 1;
    const int tid = threadIdx.x;
    const int r = tid >> 1;
    const int c0 = (tid & 1) * 32;

    float M = -1e30f;
#pragma unroll
    for (int c = 0; c < 8; c++)
        if (c < nch) M = fmaxf(M, g_am[b][c][it][r]);

    float w[8];
    float lt = 0.f;
#pragma unroll
    for (int c = 0; c < 8; c++) {
        w[c] = 0.f;
        if (c < nch) {
            w[c] = __expf(g_am[b][c][it][r] - M);
            lt += g_al[b][c][it][r] * w[c];
        }
    }
    const float inv = 1.f / lt;

    float* dst = out + ((size_t)b * SS + it * 128 + r) * DHE + c0;
#pragma unroll
    for (int j4 = 0; j4 < 8; j4++) {
        float4 acc = make_float4(0.f, 0.f, 0.f, 0.f);
#pragma unroll
        for (int c = 0; c < 8; c++)
            if (c < nch) {
                float4 v = *(const float4*)&g_aO[b][c][it][r * 64 + c0 + j4 * 4];
                acc.x = fmaf(v.x, w[c], acc.x);
                acc.y = fmaf(v.y, w[c], acc.y);
                acc.z = fmaf(v.z, w[c], acc.z);
                acc.w = fmaf(v.w, w[c], acc.w);
            }
        *(float4*)(dst + j4 * 4) =
            make_float4(acc.x * inv, acc.y * inv, acc.z * inv, acc.w * inv);
    }
}

// ---------------------------------------------------------------------------
extern "C" void kernel_launch(void* const* d_in, const int* in_sizes, int n_in,
                              void* d_out, int out_size) {
    const float* x   = (const float*)d_in[0];
    const float* wqu = (const float*)d_in[1];
    const float* wku = (const float*)d_in[2];
    const float* wvu = (const float*)d_in[3];
    const float* wqc = (const float*)d_in[4];
    const float* wkc = (const float*)d_in[5];
    const float* wvc = (const float*)d_in[6];
    float* out = (float*)d_out;

    k_cvt_x<<<2048, 256>>>(x);
    k_cvt_w<<<192, 256>>>(wqu, wku, wvu, wqc, wkc, wvc);

    const int proj_smem = 1024 + 2 * 49152;  // 99328 B
    cudaFuncSetAttribute(k_proj_mma, cudaFuncAttributeMaxDynamicSharedMemorySize, proj_smem);
    k_proj_mma<<<dim3(64, 6), 256, proj_smem>>>();

    k_vt<<<dim3(32, 4), 256>>>();

    const int pair_smem = 1024 + 65536;  // 66560 B
    cudaFuncSetAttribute(k_pair_mma, cudaFuncAttributeMaxDynamicSharedMemorySize, pair_smem);
    k_pair_mma<<<dim3(136, 4, 2), 256, pair_smem>>>();

    const int su_smem = 1024 + 2 * 65536;  // 132096 B
    cudaFuncSetAttribute(k_su_mma, cudaFuncAttributeMaxDynamicSharedMemorySize, su_smem);
    k_su_mma<<<dim3(272, 1, 4), 256, su_smem>>>();

    const int attn_smem = 1024 + 6 * 16384;  // 99328 B
    cudaFuncSetAttribute(k_attn_mma, cudaFuncAttributeMaxDynamicSharedMemorySize, attn_smem);
    k_attn_mma<<<dim3(16, 8, 4), 256, attn_smem>>>();

    k_comb<<<dim3(16, 4), 256>>>(out);
}